// round 3
// baseline (speedup 1.0000x reference)
#include <cuda_runtime.h>
#include <math.h>

#define BB 1024
#define SS 100
#define HH 512
#define GG 1536   // 3*H
#define NUSR 1000

// Scratch (device globals: allowed; no runtime allocation)
__device__ float g_xproj[(size_t)BB * SS * GG];   // [B,S,3H]
__device__ float g_gruout[(size_t)BB * SS * HH];  // [B,S,H] (unmasked)

// ---------------------------------------------------------------------------
// Kernel 1: x_proj[M=B*S, N=3H] = X[M,512] @ W_ih^T + b_ih
// 128x128x8 tiled fp32 GEMM, 256 threads, 8x8 per thread, prefetch gmem->reg.
// ---------------------------------------------------------------------------
__global__ void __launch_bounds__(256, 2)
k_xproj(const float* __restrict__ X, const float* __restrict__ W,
        const float* __restrict__ bias) {
    __shared__ float As[8][128];
    __shared__ float Bs[8][128];
    const int tid = threadIdx.x;
    const int tx = tid & 15;
    const int ty = tid >> 4;
    const int bm = blockIdx.x;   // 0..799
    const int bn = blockIdx.y;   // 0..11
    const int r  = tid >> 1;     // 0..127 local row
    const int q  = (tid & 1) * 4;

    const float* Ap = X + (size_t)(bm * 128 + r) * 512 + q;
    const float* Bp = W + (size_t)(bn * 128 + r) * 512 + q;

    float acc[8][8];
#pragma unroll
    for (int i = 0; i < 8; i++)
#pragma unroll
        for (int j = 0; j < 8; j++) acc[i][j] = 0.f;

    float4 av = *(const float4*)Ap;
    float4 bv = *(const float4*)Bp;

    for (int kt = 0; kt < 64; kt++) {
        __syncthreads();
        As[q + 0][r] = av.x; As[q + 1][r] = av.y; As[q + 2][r] = av.z; As[q + 3][r] = av.w;
        Bs[q + 0][r] = bv.x; Bs[q + 1][r] = bv.y; Bs[q + 2][r] = bv.z; Bs[q + 3][r] = bv.w;
        __syncthreads();
        if (kt < 63) {
            av = *(const float4*)(Ap + (kt + 1) * 8);
            bv = *(const float4*)(Bp + (kt + 1) * 8);
        }
#pragma unroll
        for (int k = 0; k < 8; k++) {
            float4 a0 = *(const float4*)&As[k][ty * 8];
            float4 a1 = *(const float4*)&As[k][ty * 8 + 4];
            float4 b0 = *(const float4*)&Bs[k][tx * 8];
            float4 b1 = *(const float4*)&Bs[k][tx * 8 + 4];
            float a[8] = {a0.x, a0.y, a0.z, a0.w, a1.x, a1.y, a1.z, a1.w};
            float b[8] = {b0.x, b0.y, b0.z, b0.w, b1.x, b1.y, b1.z, b1.w};
#pragma unroll
            for (int i = 0; i < 8; i++)
#pragma unroll
                for (int j = 0; j < 8; j++) acc[i][j] += a[i] * b[j];
        }
    }

    const int n0 = bn * 128 + tx * 8;
    float bias8[8];
#pragma unroll
    for (int j = 0; j < 8; j++) bias8[j] = bias[n0 + j];
#pragma unroll
    for (int i = 0; i < 8; i++) {
        int m = bm * 128 + ty * 8 + i;
        float* o = g_xproj + (size_t)m * GG + n0;
        float4 v0, v1;
        v0.x = acc[i][0] + bias8[0]; v0.y = acc[i][1] + bias8[1];
        v0.z = acc[i][2] + bias8[2]; v0.w = acc[i][3] + bias8[3];
        v1.x = acc[i][4] + bias8[4]; v1.y = acc[i][5] + bias8[5];
        v1.z = acc[i][6] + bias8[6]; v1.w = acc[i][7] + bias8[7];
        *(float4*)(o)     = v0;
        *(float4*)(o + 4) = v1;
    }
}

// ---------------------------------------------------------------------------
// Kernel 2: GRU recurrence. Each CTA owns 8 batch rows and runs all 100 steps.
// Per step: gh[8,1536] = h[8,512] @ W_hh^T  (W_hh streamed through SMEM in
// k-tiles of 8 with register prefetch), then fused gate epilogue.
// Dynamic SMEM: h_s[8][513] + w_s[8][1536] + gh_s[8][1536] = 114,720 B.
// ---------------------------------------------------------------------------
#define SMEM_GRU_BYTES ((8 * 513 + 8 * 1536 + 8 * 1536) * 4)

__global__ void __launch_bounds__(256, 1)
k_gru(const float* __restrict__ h0, const float* __restrict__ Whh,
      const float* __restrict__ bhh) {
    extern __shared__ float sm[];
    float* h_s  = sm;                 // [8][513]
    float* w_s  = sm + 8 * 513;       // [8 k][1536 n]
    float* gh_s = w_s + 8 * 1536;     // [8 m][1536 n]
    const int tid = threadIdx.x;
    const int b0 = blockIdx.x * 8;

    for (int idx = tid; idx < 8 * 512; idx += 256) {
        int m = idx >> 9, j = idx & 511;
        h_s[m * 513 + j] = h0[(size_t)(b0 + m) * 512 + j];
    }
    float bh[6];
#pragma unroll
    for (int j = 0; j < 6; j++) bh[j] = bhh[tid + 256 * j];
    __syncthreads();

    for (int t = 0; t < SS; t++) {
        float acc[8][6];
#pragma unroll
        for (int m = 0; m < 8; m++)
#pragma unroll
            for (int j = 0; j < 6; j++) acc[m][j] = 0.f;

        // prefetch k-tile 0 of W_hh (12 float4 per thread cover 1536x8 tile)
        float4 vb[12];
#pragma unroll
        for (int j = 0; j < 12; j++) {
            int id = tid + 256 * j;
            vb[j] = *(const float4*)(Whh + (size_t)(id >> 1) * 512 + ((id & 1) << 2));
        }

        for (int kt = 0; kt < 64; kt++) {
            __syncthreads();
#pragma unroll
            for (int j = 0; j < 12; j++) {
                int id = tid + 256 * j;
                int rr = id >> 1, qq = (id & 1) * 4;
                w_s[(qq + 0) * 1536 + rr] = vb[j].x;
                w_s[(qq + 1) * 1536 + rr] = vb[j].y;
                w_s[(qq + 2) * 1536 + rr] = vb[j].z;
                w_s[(qq + 3) * 1536 + rr] = vb[j].w;
            }
            __syncthreads();
            if (kt < 63) {
#pragma unroll
                for (int j = 0; j < 12; j++) {
                    int id = tid + 256 * j;
                    vb[j] = *(const float4*)(Whh + (size_t)(id >> 1) * 512 +
                                             (kt + 1) * 8 + ((id & 1) << 2));
                }
            }
#pragma unroll
            for (int k = 0; k < 8; k++) {
                float a[8];
#pragma unroll
                for (int m = 0; m < 8; m++) a[m] = h_s[m * 513 + kt * 8 + k];
                float w[6];
#pragma unroll
                for (int j = 0; j < 6; j++) w[j] = w_s[k * 1536 + tid + 256 * j];
#pragma unroll
                for (int m = 0; m < 8; m++)
#pragma unroll
                    for (int j = 0; j < 6; j++) acc[m][j] += a[m] * w[j];
            }
        }
        __syncthreads();
#pragma unroll
        for (int m = 0; m < 8; m++)
#pragma unroll
            for (int j = 0; j < 6; j++)
                gh_s[m * 1536 + tid + 256 * j] = acc[m][j] + bh[j];
        __syncthreads();

        // gates
        for (int idx = tid; idx < 8 * 512; idx += 256) {
            int m = idx >> 9, j = idx & 511;
            const float* xp = g_xproj + ((size_t)((b0 + m) * SS + t)) * GG;
            float xr = xp[j], xz = xp[512 + j], xn = xp[1024 + j];
            float hr = gh_s[m * 1536 + j];
            float hz = gh_s[m * 1536 + 512 + j];
            float hn = gh_s[m * 1536 + 1024 + j];
            float rg = 1.f / (1.f + expf(-(xr + hr)));
            float zg = 1.f / (1.f + expf(-(xz + hz)));
            float ng = tanhf(xn + rg * hn);
            float hv = h_s[m * 513 + j];
            float hnew = (1.f - zg) * ng + zg * hv;
            h_s[m * 513 + j] = hnew;
            g_gruout[((size_t)(b0 + m) * SS + t) * HH + j] = hnew;
        }
        __syncthreads();
    }
}

// ---------------------------------------------------------------------------
// Kernel 3: per-batch-row attention + softmax + weighted pooling.
// One CTA per b. Masked GRU output (mask applied to hidden vec, per reference)
// cached in SMEM [100][513]; Wa_b streamed in 64-o x 16-k tiles.
// scores[s] = sum_o Ws[o]*tanh(E[s,o]+ba[o])   (bs dropped: softmax-invariant)
// Dynamic SMEM: 100*513 + 16*64 + 128 floats = 209,808 B.
// ---------------------------------------------------------------------------
#define SMEM_ATTN_BYTES ((100 * 513 + 16 * 64 + 128) * 4)

__global__ void __launch_bounds__(256, 1)
k_attn(const float* __restrict__ reps, const int* __restrict__ counts,
       const int* __restrict__ users, const float* __restrict__ Wa,
       const float* __restrict__ ba, const float* __restrict__ Wsv,
       float* __restrict__ outp) {
    extern __shared__ float sm[];
    float* out_s = sm;                  // [100][513]
    float* Bsm   = sm + 100 * 513;      // [16 k][64 o]
    float* score = Bsm + 16 * 64;       // [128]
    const int tid = threadIdx.x;
    const int b = blockIdx.x;
    const int cnt = counts[b];
    const int u = users[b];

    for (int idx = tid; idx < 100 * 512; idx += 256) {
        int s = idx >> 9, h = idx & 511;
        float v = g_gruout[((size_t)b * SS + s) * HH + h];
        if (s >= cnt) v -= 1000000.0f;
        out_s[s * 513 + h] = v;
    }
    if (tid < 128) score[tid] = 0.f;
    __syncthreads();

    const int tx = tid & 15;   // o-group (4 cols each)
    const int ty = tid >> 4;   // s-group (7 rows each)
    int srow[7];
#pragma unroll
    for (int i = 0; i < 7; i++) {
        int s = ty * 7 + i;
        srow[i] = (s < 100 ? s : 99) * 513;
    }
    const float* WaU = Wa + (size_t)u * (512 * 512);
    const int rB = tid >> 2;
    const int qB = (tid & 3) * 4;

    for (int c = 0; c < 8; c++) {
        float acc[7][4];
#pragma unroll
        for (int i = 0; i < 7; i++)
#pragma unroll
            for (int j = 0; j < 4; j++) acc[i][j] = 0.f;

        const float* wp = WaU + (size_t)(c * 64 + rB) * 512 + qB;
        float4 v = *(const float4*)wp;

        for (int kt = 0; kt < 32; kt++) {
            __syncthreads();
            Bsm[(qB + 0) * 64 + rB] = v.x;
            Bsm[(qB + 1) * 64 + rB] = v.y;
            Bsm[(qB + 2) * 64 + rB] = v.z;
            Bsm[(qB + 3) * 64 + rB] = v.w;
            __syncthreads();
            if (kt < 31) v = *(const float4*)(wp + (kt + 1) * 16);
#pragma unroll
            for (int k = 0; k < 16; k++) {
                float a[7];
#pragma unroll
                for (int i = 0; i < 7; i++) a[i] = out_s[srow[i] + kt * 16 + k];
                float4 wv = *(const float4*)&Bsm[k * 64 + tx * 4];
#pragma unroll
                for (int i = 0; i < 7; i++) {
                    acc[i][0] += a[i] * wv.x;
                    acc[i][1] += a[i] * wv.y;
                    acc[i][2] += a[i] * wv.z;
                    acc[i][3] += a[i] * wv.w;
                }
            }
        }
        float ba4[4], ws4[4];
#pragma unroll
        for (int j = 0; j < 4; j++) {
            int o = c * 64 + tx * 4 + j;
            ba4[j] = ba[(size_t)u * 512 + o];
            ws4[j] = Wsv[(size_t)u * 512 + o];
        }
#pragma unroll
        for (int i = 0; i < 7; i++) {
            int s = ty * 7 + i;
            if (s < 100) {
                float p = 0.f;
#pragma unroll
                for (int j = 0; j < 4; j++) p += ws4[j] * tanhf(acc[i][j] + ba4[j]);
                atomicAdd(&score[s], p);
            }
        }
    }
    __syncthreads();

    // softmax over 100 scores (warp 0)
    if (tid < 32) {
        float mx = -1e30f;
        for (int s = tid; s < 100; s += 32) mx = fmaxf(mx, score[s]);
#pragma unroll
        for (int o = 16; o > 0; o >>= 1) mx = fmaxf(mx, __shfl_xor_sync(0xffffffffu, mx, o));
        float ssum = 0.f;
        for (int s = tid; s < 100; s += 32) {
            float e = expf(score[s] - mx);
            score[s] = e;
            ssum += e;
        }
#pragma unroll
        for (int o = 16; o > 0; o >>= 1) ssum += __shfl_xor_sync(0xffffffffu, ssum, o);
        float inv = 1.f / ssum;
        for (int s = tid; s < 100; s += 32) score[s] *= inv;
    }
    __syncthreads();

    // user_repr = sum_s attn[s] * reps[b,s,:]
    const float* rb = reps + (size_t)b * (SS * HH);
    for (int h = tid; h < 512; h += 256) {
        float a0 = 0.f;
        for (int s = 0; s < 100; s++) a0 += score[s] * rb[s * 512 + h];
        outp[(size_t)b * 512 + h] = a0;
    }
}

// ---------------------------------------------------------------------------
extern "C" void kernel_launch(void* const* d_in, const int* in_sizes, int n_in,
                              void* d_out, int out_size) {
    const float* reps   = (const float*)d_in[0];
    const float* hidden = (const float*)d_in[1];
    const int*   counts = (const int*)d_in[2];
    const int*   users  = (const int*)d_in[3];
    const float* W_ih   = (const float*)d_in[4];
    const float* W_hh   = (const float*)d_in[5];
    const float* b_ih   = (const float*)d_in[6];
    const float* b_hh   = (const float*)d_in[7];
    const float* Wa     = (const float*)d_in[8];
    const float* ba     = (const float*)d_in[9];
    const float* Ws     = (const float*)d_in[10];
    // d_in[11] = bs: additive per-row constant on scores -> softmax-invariant.
    float* out = (float*)d_out;

    cudaFuncSetAttribute(k_gru, cudaFuncAttributeMaxDynamicSharedMemorySize,
                         SMEM_GRU_BYTES);
    cudaFuncSetAttribute(k_attn, cudaFuncAttributeMaxDynamicSharedMemorySize,
                         SMEM_ATTN_BYTES);

    dim3 g1(800, 12);
    k_xproj<<<g1, 256>>>(reps, W_ih, b_ih);
    k_gru<<<BB / 8, 256, SMEM_GRU_BYTES>>>(hidden, W_hh, b_hh);
    k_attn<<<BB, 256, SMEM_ATTN_BYTES>>>(reps, counts, users, Wa, ba, Ws, out);
}

// round 8
// speedup vs baseline: 1.2032x; 1.2032x over previous
#include <cuda_runtime.h>
#include <cuda_bf16.h>
#include <math.h>
#include <stdint.h>

#define BB 1024
#define SS 100
#define HH 512
#define GG 1536   // 3*H
#define NUSR 1000

// ---------------------------------------------------------------------------
// Scratch (device globals: allowed; no runtime allocation)
// ---------------------------------------------------------------------------
__device__ float g_xproj[(size_t)BB * SS * GG];            // [B,S,3H] fp32
__device__ __nv_bfloat16 g_xh[(size_t)BB * SS * HH];       // X hi
__device__ __nv_bfloat16 g_xl[(size_t)BB * SS * HH];       // X lo
__device__ __nv_bfloat16 g_wh[(size_t)GG * HH];            // W_ih hi
__device__ __nv_bfloat16 g_wl[(size_t)GG * HH];            // W_ih lo
__device__ __nv_bfloat16 g_wah[(size_t)NUSR * HH * HH];    // Wa hi
__device__ __nv_bfloat16 g_wal[(size_t)NUSR * HH * HH];    // Wa lo
__device__ __nv_bfloat16 g_hh[(size_t)BB * 128 * HH];      // GRU h hi (rows 100..127 stay 0)
__device__ __nv_bfloat16 g_hl[(size_t)BB * 128 * HH];      // GRU h lo
__device__ float g_C[(size_t)NUSR * HH];                   // exact col-sums of Wa

// ---------------------------------------------------------------------------
// Portable tensor-core primitives (compile for compute_103, no 'a' features)
// ---------------------------------------------------------------------------
__device__ __forceinline__ uint32_t smem_u32(const void* p) {
    uint32_t a;
    asm("{ .reg .u64 t; cvta.to.shared.u64 t, %1; cvt.u32.u64 %0, t; }"
        : "=r"(a) : "l"(p));
    return a;
}

#define CP_ASYNC16(sa, ga) \
    asm volatile("cp.async.cg.shared.global [%0], [%1], 16;" :: "r"(sa), "l"(ga))
#define CP_COMMIT() asm volatile("cp.async.commit_group;")
#define CP_WAIT1() asm volatile("cp.async.wait_group 1;" ::: "memory")
#define CP_WAIT0() asm volatile("cp.async.wait_group 0;" ::: "memory")

#define LDMX4(r0, r1, r2, r3, a) \
    asm volatile("ldmatrix.sync.aligned.m8n8.x4.shared.b16 {%0,%1,%2,%3}, [%4];" \
                 : "=r"(r0), "=r"(r1), "=r"(r2), "=r"(r3) : "r"(a))

#define MMA_BF16(d, a, b) \
    asm volatile( \
        "mma.sync.aligned.m16n8k16.row.col.f32.bf16.bf16.f32 " \
        "{%0,%1,%2,%3}, {%4,%5,%6,%7}, {%8,%9}, {%0,%1,%2,%3};" \
        : "+f"((d)[0]), "+f"((d)[1]), "+f"((d)[2]), "+f"((d)[3]) \
        : "r"((a)[0]), "r"((a)[1]), "r"((a)[2]), "r"((a)[3]), \
          "r"((b)[0]), "r"((b)[1]))

// ---------------------------------------------------------------------------
// Kernel A: fp32 -> bf16 hi/lo split (generic, float4-granular)
// ---------------------------------------------------------------------------
__global__ void k_split(const float* __restrict__ src, __nv_bfloat16* __restrict__ hi,
                        __nv_bfloat16* __restrict__ lo, size_t n4) {
    size_t i = (size_t)blockIdx.x * 256 + threadIdx.x;
    if (i >= n4) return;
    float4 v = ((const float4*)src)[i];
    float f[4] = {v.x, v.y, v.z, v.w};
    union { __nv_bfloat16 h[4]; uint2 u; } H;
    union { __nv_bfloat16 h[4]; uint2 u; } L;
#pragma unroll
    for (int j = 0; j < 4; j++) {
        __nv_bfloat16 hh = __float2bfloat16(f[j]);
        H.h[j] = hh;
        L.h[j] = __float2bfloat16(f[j] - __bfloat162float(hh));
    }
    *(uint2*)(hi + i * 4) = H.u;
    *(uint2*)(lo + i * 4) = L.u;
}

// ---------------------------------------------------------------------------
// Kernel B: exact fp32 column sums C[u][o] = sum_k Wa[u][o][k]
// one warp per (u, o) row.  grid (NUSR, 64), block 256.
// ---------------------------------------------------------------------------
__global__ void k_colsum(const float* __restrict__ Wa, float* __restrict__ C) {
    const int u = blockIdx.x;
    const int o = blockIdx.y * 8 + (threadIdx.x >> 5);
    const int lane = threadIdx.x & 31;
    const float* row = Wa + ((size_t)u * 512 + o) * 512;
    float s = 0.f;
#pragma unroll
    for (int q = 0; q < 4; q++) {
        float4 v = ((const float4*)row)[lane + q * 32];
        s += v.x + v.y + v.z + v.w;
    }
#pragma unroll
    for (int ofs = 16; ofs; ofs >>= 1) s += __shfl_xor_sync(0xffffffffu, s, ofs);
    if (lane == 0) C[(size_t)u * 512 + o] = s;
}

// ---------------------------------------------------------------------------
// Kernel 1: x_proj = X @ W_ih^T + b_ih  via mma.sync bf16 split-3.
// CTA tile 128(M) x 256(N), K chunks of 16, 512 threads = 16 warps (2m x 8n),
// warp tile 64x32.  SMEM rows padded to 48B (conflict-free ldmatrix).
// Stage = Ah[128][48] Al Bh[256][48] Bl = 36864B, double buffered = 73728B.
// ---------------------------------------------------------------------------
#define XP_AH 0
#define XP_AL 6144
#define XP_BH 12288
#define XP_BL 24576
#define XP_STG 36864
#define XP_SMEM (2 * XP_STG)

__global__ void __launch_bounds__(512, 1)
k_xproj_mma(const float* __restrict__ bias) {
    extern __shared__ char smx[];
    const uint32_t sb = smem_u32(smx);
    const int tid = threadIdx.x;
    const int wid = tid >> 5, lane = tid & 31;
    const int wm = wid >> 3, wn = wid & 7;      // 2 x 8 warp grid
    const int bm = blockIdx.x;                  // 0..799
    const int bn = blockIdx.y;                  // 0..5
    const size_t m0 = (size_t)bm * 128;
    const size_t n0 = (size_t)bn * 256;

    // per-thread cp.async assignments (3 x 16B per chunk)
    // Ah/Al: 256 transfers (128 rows x 2), Bh: 512, Bl: 512.
    const int ia  = tid & 255;                 // Ah or Al index
    const int ar  = ia >> 1, ac = ia & 1;
    const int br  = tid >> 1, bc = tid & 1;    // B index (512)
    const bool isAl = (tid >= 256);

    float acc[4][4][4];
#pragma unroll
    for (int i = 0; i < 4; i++)
#pragma unroll
        for (int j = 0; j < 4; j++)
#pragma unroll
            for (int q = 0; q < 4; q++) acc[i][j][q] = 0.f;

    // ldmatrix base offsets (within a stage)
    const uint32_t a_lane_off =
        (uint32_t)((wm * 64 + (lane & 15)) * 48 + (lane >> 4) * 16);
    const uint32_t b_lane_off =
        (uint32_t)((wn * 32 + (lane & 7) + (lane >> 4) * 8) * 48 +
                   ((lane >> 3) & 1) * 16);

    // issue chunk 0
    {
        const int k0 = 0;
        uint32_t st = sb;
        const __nv_bfloat16* gA = isAl ? g_xl : g_xh;
        CP_ASYNC16(st + (isAl ? XP_AL : XP_AH) + ar * 48 + ac * 16,
                   gA + (m0 + ar) * 512 + k0 + ac * 8);
        CP_ASYNC16(st + XP_BH + br * 48 + bc * 16,
                   g_wh + (n0 + br) * 512 + k0 + bc * 8);
        CP_ASYNC16(st + XP_BL + br * 48 + bc * 16,
                   g_wl + (n0 + br) * 512 + k0 + bc * 8);
        CP_COMMIT();
    }

    for (int c = 0; c < 32; c++) {
        const uint32_t cur = sb + (uint32_t)(c & 1) * XP_STG;
        if (c < 31) {
            const int k0 = (c + 1) * 16;
            uint32_t st = sb + (uint32_t)((c + 1) & 1) * XP_STG;
            const __nv_bfloat16* gA = isAl ? g_xl : g_xh;
            CP_ASYNC16(st + (isAl ? XP_AL : XP_AH) + ar * 48 + ac * 16,
                       gA + (m0 + ar) * 512 + k0 + ac * 8);
            CP_ASYNC16(st + XP_BH + br * 48 + bc * 16,
                       g_wh + (n0 + br) * 512 + k0 + bc * 8);
            CP_ASYNC16(st + XP_BL + br * 48 + bc * 16,
                       g_wl + (n0 + br) * 512 + k0 + bc * 8);
            CP_COMMIT();
            CP_WAIT1();
        } else {
            CP_WAIT0();
        }
        __syncthreads();

        uint32_t bh[4][2], bl[4][2];
        {
            uint32_t r0, r1, r2, r3;
            LDMX4(r0, r1, r2, r3, cur + XP_BH + b_lane_off);
            bh[0][0] = r0; bh[0][1] = r1; bh[1][0] = r2; bh[1][1] = r3;
            LDMX4(r0, r1, r2, r3, cur + XP_BH + b_lane_off + 16 * 48);
            bh[2][0] = r0; bh[2][1] = r1; bh[3][0] = r2; bh[3][1] = r3;
            LDMX4(r0, r1, r2, r3, cur + XP_BL + b_lane_off);
            bl[0][0] = r0; bl[0][1] = r1; bl[1][0] = r2; bl[1][1] = r3;
            LDMX4(r0, r1, r2, r3, cur + XP_BL + b_lane_off + 16 * 48);
            bl[2][0] = r0; bl[2][1] = r1; bl[3][0] = r2; bl[3][1] = r3;
        }
#pragma unroll
        for (int mi = 0; mi < 4; mi++) {
            uint32_t ah[4], al[4];
            LDMX4(ah[0], ah[1], ah[2], ah[3], cur + XP_AH + a_lane_off + mi * 16 * 48);
            LDMX4(al[0], al[1], al[2], al[3], cur + XP_AL + a_lane_off + mi * 16 * 48);
#pragma unroll
            for (int nj = 0; nj < 4; nj++) {
                MMA_BF16(acc[mi][nj], ah, bh[nj]);
                MMA_BF16(acc[mi][nj], ah, bl[nj]);
                MMA_BF16(acc[mi][nj], al, bh[nj]);
            }
        }
        __syncthreads();
    }

    // epilogue: bias + store fp32
    const int q = lane >> 2, cc = (lane & 3) * 2;
#pragma unroll
    for (int mi = 0; mi < 4; mi++) {
        const size_t r0 = m0 + wm * 64 + mi * 16 + q;
#pragma unroll
        for (int nj = 0; nj < 4; nj++) {
            const size_t nn = n0 + wn * 32 + nj * 8 + cc;
            float b0 = __ldg(bias + nn), b1 = __ldg(bias + nn + 1);
            float2 v0 = {acc[mi][nj][0] + b0, acc[mi][nj][1] + b1};
            float2 v1 = {acc[mi][nj][2] + b0, acc[mi][nj][3] + b1};
            *(float2*)(g_xproj + r0 * GG + nn) = v0;
            *(float2*)(g_xproj + (r0 + 8) * GG + nn) = v1;
        }
    }
}

// ---------------------------------------------------------------------------
// Kernel 2: GRU recurrence (SIMT fp32, known good). Epilogue now also emits
// bf16 hi/lo of h into g_hh/g_hl (rows 100..127 of each b remain zero).
// ---------------------------------------------------------------------------
#define SMEM_GRU_BYTES ((8 * 513 + 8 * 1536 + 8 * 1536) * 4)

__global__ void __launch_bounds__(256, 1)
k_gru(const float* __restrict__ h0, const float* __restrict__ Whh,
      const float* __restrict__ bhh) {
    extern __shared__ float sm[];
    float* h_s  = sm;
    float* w_s  = sm + 8 * 513;
    float* gh_s = w_s + 8 * 1536;
    const int tid = threadIdx.x;
    const int b0 = blockIdx.x * 8;

    for (int idx = tid; idx < 8 * 512; idx += 256) {
        int m = idx >> 9, j = idx & 511;
        h_s[m * 513 + j] = h0[(size_t)(b0 + m) * 512 + j];
    }
    float bh[6];
#pragma unroll
    for (int j = 0; j < 6; j++) bh[j] = bhh[tid + 256 * j];
    __syncthreads();

    for (int t = 0; t < SS; t++) {
        float acc[8][6];
#pragma unroll
        for (int m = 0; m < 8; m++)
#pragma unroll
            for (int j = 0; j < 6; j++) acc[m][j] = 0.f;

        float4 vb[12];
#pragma unroll
        for (int j = 0; j < 12; j++) {
            int id = tid + 256 * j;
            vb[j] = *(const float4*)(Whh + (size_t)(id >> 1) * 512 + ((id & 1) << 2));
        }

        for (int kt = 0; kt < 64; kt++) {
            __syncthreads();
#pragma unroll
            for (int j = 0; j < 12; j++) {
                int id = tid + 256 * j;
                int rr = id >> 1, qq = (id & 1) * 4;
                w_s[(qq + 0) * 1536 + rr] = vb[j].x;
                w_s[(qq + 1) * 1536 + rr] = vb[j].y;
                w_s[(qq + 2) * 1536 + rr] = vb[j].z;
                w_s[(qq + 3) * 1536 + rr] = vb[j].w;
            }
            __syncthreads();
            if (kt < 63) {
#pragma unroll
                for (int j = 0; j < 12; j++) {
                    int id = tid + 256 * j;
                    vb[j] = *(const float4*)(Whh + (size_t)(id >> 1) * 512 +
                                             (kt + 1) * 8 + ((id & 1) << 2));
                }
            }
#pragma unroll
            for (int k = 0; k < 8; k++) {
                float a[8];
#pragma unroll
                for (int m = 0; m < 8; m++) a[m] = h_s[m * 513 + kt * 8 + k];
                float w[6];
#pragma unroll
                for (int j = 0; j < 6; j++) w[j] = w_s[k * 1536 + tid + 256 * j];
#pragma unroll
                for (int m = 0; m < 8; m++)
#pragma unroll
                    for (int j = 0; j < 6; j++) acc[m][j] += a[m] * w[j];
            }
        }
        __syncthreads();
#pragma unroll
        for (int m = 0; m < 8; m++)
#pragma unroll
            for (int j = 0; j < 6; j++)
                gh_s[m * 1536 + tid + 256 * j] = acc[m][j] + bh[j];
        __syncthreads();

        for (int idx = tid; idx < 8 * 512; idx += 256) {
            int m = idx >> 9, j = idx & 511;
            const float* xp = g_xproj + ((size_t)((b0 + m) * SS + t)) * GG;
            float xr = xp[j], xz = xp[512 + j], xn = xp[1024 + j];
            float hr = gh_s[m * 1536 + j];
            float hz = gh_s[m * 1536 + 512 + j];
            float hn = gh_s[m * 1536 + 1024 + j];
            float rg = 1.f / (1.f + expf(-(xr + hr)));
            float zg = 1.f / (1.f + expf(-(xz + hz)));
            float ng = tanhf(xn + rg * hn);
            float hv = h_s[m * 513 + j];
            float hnew = (1.f - zg) * ng + zg * hv;
            h_s[m * 513 + j] = hnew;
            size_t ho = ((size_t)(b0 + m) * 128 + t) * 512 + j;
            __nv_bfloat16 hb = __float2bfloat16(hnew);
            g_hh[ho] = hb;
            g_hl[ho] = __float2bfloat16(hnew - __bfloat162float(hb));
        }
        __syncthreads();
    }
}

// ---------------------------------------------------------------------------
// Kernel 3: attention via mma.sync. One CTA per b, 256 thr = 8 warps (2m x 4n),
// warp tile 64x32 -> pass covers N=128; 4 passes over o.  K chunks of 16,
// cp.async double buffer.  G computed on UNMASKED h; mask handled exactly via
// arg -= 1e6 * C[u][o]  (C = exact fp32 col-sum).  Epilogue per pass applies
// tanh + Ws dot in registers, quad-shfl reduce, atomicAdd to smem scores.
// SMEM: [0) ba 2048 | 2048 ws | 4096 C 2048 | 6144 score 512 | 7168 stages.
// Stage = Ah[128][48] Al Bh[128][48] Bl = 24576B x2 = 49152.
// ---------------------------------------------------------------------------
#define AT_BASE 7168
#define AT_AH 0
#define AT_AL 6144
#define AT_BH 12288
#define AT_BL 18432
#define AT_STG 24576
#define AT_SMEM (AT_BASE + 2 * AT_STG)

__global__ void __launch_bounds__(256, 1)
k_attn_mma(const float* __restrict__ reps, const int* __restrict__ counts,
           const int* __restrict__ users, const float* __restrict__ ba,
           const float* __restrict__ Wsv, float* __restrict__ outp) {
    extern __shared__ char smx[];
    const uint32_t sb = smem_u32(smx);
    float* ba_s  = (float*)(smx);
    float* ws_s  = (float*)(smx + 2048);
    float* C_s   = (float*)(smx + 4096);
    float* score = (float*)(smx + 6144);
    const int tid = threadIdx.x;
    const int wid = tid >> 5, lane = tid & 31;
    const int wm = wid >> 2, wn = wid & 3;      // 2 x 4 warp grid
    const int b = blockIdx.x;
    const int cnt = counts[b];
    const int u = users[b];

    ba_s[tid]       = ba[(size_t)u * 512 + tid];
    ba_s[tid + 256] = ba[(size_t)u * 512 + 256 + tid];
    ws_s[tid]       = Wsv[(size_t)u * 512 + tid];
    ws_s[tid + 256] = Wsv[(size_t)u * 512 + 256 + tid];
    C_s[tid]        = g_C[(size_t)u * 512 + tid];
    C_s[tid + 256]  = g_C[(size_t)u * 512 + 256 + tid];
    if (tid < 128) score[tid] = 0.f;
    __syncthreads();

    const __nv_bfloat16* Ahg = g_hh + (size_t)b * 128 * 512;
    const __nv_bfloat16* Alg = g_hl + (size_t)b * 128 * 512;
    const __nv_bfloat16* Bhg = g_wah + (size_t)u * 512 * 512;
    const __nv_bfloat16* Blg = g_wal + (size_t)u * 512 * 512;

    // per-thread cp.async: 4 x 16B per chunk (each array 256 transfers)
    const int tr = tid >> 1, tc = tid & 1;

    const uint32_t a_lane_off =
        (uint32_t)((wm * 64 + (lane & 15)) * 48 + (lane >> 4) * 16);
    const uint32_t b_lane_off =
        (uint32_t)((wn * 32 + (lane & 7) + (lane >> 4) * 8) * 48 +
                   ((lane >> 3) & 1) * 16);
    const int q = lane >> 2, cc = (lane & 3) * 2;

    // flattened it = np*32 + c  (np = o-pass, c = k-chunk)
    // issue it=0
    {
        uint32_t st = sb + AT_BASE;
        CP_ASYNC16(st + AT_AH + tr * 48 + tc * 16, Ahg + tr * 512 + tc * 8);
        CP_ASYNC16(st + AT_AL + tr * 48 + tc * 16, Alg + tr * 512 + tc * 8);
        CP_ASYNC16(st + AT_BH + tr * 48 + tc * 16, Bhg + tr * 512 + tc * 8);
        CP_ASYNC16(st + AT_BL + tr * 48 + tc * 16, Blg + tr * 512 + tc * 8);
        CP_COMMIT();
    }

    float acc[4][4][4];
    for (int it = 0; it < 128; it++) {
        const int np = it >> 5, c = it & 31;
        if (c == 0) {
#pragma unroll
            for (int i = 0; i < 4; i++)
#pragma unroll
                for (int j = 0; j < 4; j++)
#pragma unroll
                    for (int z = 0; z < 4; z++) acc[i][j][z] = 0.f;
        }
        const uint32_t cur = sb + AT_BASE + (uint32_t)(it & 1) * AT_STG;
        if (it < 127) {
            const int np2 = (it + 1) >> 5, c2 = (it + 1) & 31;
            const int k0 = c2 * 16;
            uint32_t st = sb + AT_BASE + (uint32_t)((it + 1) & 1) * AT_STG;
            CP_ASYNC16(st + AT_AH + tr * 48 + tc * 16,
                       Ahg + tr * 512 + k0 + tc * 8);
            CP_ASYNC16(st + AT_AL + tr * 48 + tc * 16,
                       Alg + tr * 512 + k0 + tc * 8);
            CP_ASYNC16(st + AT_BH + tr * 48 + tc * 16,
                       Bhg + (size_t)(np2 * 128 + tr) * 512 + k0 + tc * 8);
            CP_ASYNC16(st + AT_BL + tr * 48 + tc * 16,
                       Blg + (size_t)(np2 * 128 + tr) * 512 + k0 + tc * 8);
            CP_COMMIT();
            CP_WAIT1();
        } else {
            CP_WAIT0();
        }
        __syncthreads();

        uint32_t bh[4][2], bl[4][2];
        {
            uint32_t r0, r1, r2, r3;
            LDMX4(r0, r1, r2, r3, cur + AT_BH + b_lane_off);
            bh[0][0] = r0; bh[0][1] = r1; bh[1][0] = r2; bh[1][1] = r3;
            LDMX4(r0, r1, r2, r3, cur + AT_BH + b_lane_off + 16 * 48);
            bh[2][0] = r0; bh[2][1] = r1; bh[3][0] = r2; bh[3][1] = r3;
            LDMX4(r0, r1, r2, r3, cur + AT_BL + b_lane_off);
            bl[0][0] = r0; bl[0][1] = r1; bl[1][0] = r2; bl[1][1] = r3;
            LDMX4(r0, r1, r2, r3, cur + AT_BL + b_lane_off + 16 * 48);
            bl[2][0] = r0; bl[2][1] = r1; bl[3][0] = r2; bl[3][1] = r3;
        }
#pragma unroll
        for (int mi = 0; mi < 4; mi++) {
            uint32_t ah[4], al[4];
            LDMX4(ah[0], ah[1], ah[2], ah[3], cur + AT_AH + a_lane_off + mi * 16 * 48);
            LDMX4(al[0], al[1], al[2], al[3], cur + AT_AL + a_lane_off + mi * 16 * 48);
#pragma unroll
            for (int nj = 0; nj < 4; nj++) {
                MMA_BF16(acc[mi][nj], ah, bh[nj]);
                MMA_BF16(acc[mi][nj], ah, bl[nj]);
                MMA_BF16(acc[mi][nj], al, bh[nj]);
            }
        }
        __syncthreads();

        if (c == 31) {
            // pass epilogue: tanh + Ws dot, reduce over this warp's 32 o-cols
#pragma unroll
            for (int mi = 0; mi < 4; mi++) {
                const int s0 = wm * 64 + mi * 16 + q;
#pragma unroll
                for (int half = 0; half < 2; half++) {
                    const int s = s0 + half * 8;
                    const bool valid = (s < 100);
                    const float msk = (valid && s >= cnt) ? 1000000.0f : 0.0f;
                    float psum = 0.f;
#pragma unroll
                    for (int nj = 0; nj < 4; nj++) {
                        const int o0 = np * 128 + wn * 32 + nj * 8 + cc;
                        float a0 = acc[mi][nj][half * 2 + 0] + ba_s[o0] - msk * C_s[o0];
                        float a1 = acc[mi][nj][half * 2 + 1] + ba_s[o0 + 1] - msk * C_s[o0 + 1];
                        psum += ws_s[o0] * tanhf(a0) + ws_s[o0 + 1] * tanhf(a1);
                    }
                    psum += __shfl_xor_sync(0xffffffffu, psum, 1);
                    psum += __shfl_xor_sync(0xffffffffu, psum, 2);
                    if ((lane & 3) == 0 && valid) atomicAdd(&score[s], psum);
                }
            }
        }
    }
    __syncthreads();

    // softmax over 100 scores (warp 0)
    if (tid < 32) {
        float mx = -1e30f;
        for (int s = tid; s < 100; s += 32) mx = fmaxf(mx, score[s]);
#pragma unroll
        for (int o = 16; o > 0; o >>= 1) mx = fmaxf(mx, __shfl_xor_sync(0xffffffffu, mx, o));
        float ssum = 0.f;
        for (int s = tid; s < 100; s += 32) {
            float e = expf(score[s] - mx);
            score[s] = e;
            ssum += e;
        }
#pragma unroll
        for (int o = 16; o > 0; o >>= 1) ssum += __shfl_xor_sync(0xffffffffu, ssum, o);
        float inv = 1.f / ssum;
        for (int s = tid; s < 100; s += 32) score[s] *= inv;
    }
    __syncthreads();

    // pooling: out[b,h] = sum_s attn[s] * reps[b,s,h]
    const float* rb = reps + (size_t)b * (SS * HH);
    for (int h = tid; h < 512; h += 256) {
        float a0 = 0.f;
        for (int s = 0; s < 100; s++) a0 += score[s] * rb[s * 512 + h];
        outp[(size_t)b * 512 + h] = a0;
    }
}

// ---------------------------------------------------------------------------
extern "C" void kernel_launch(void* const* d_in, const int* in_sizes, int n_in,
                              void* d_out, int out_size) {
    const float* reps   = (const float*)d_in[0];
    const float* hidden = (const float*)d_in[1];
    const int*   counts = (const int*)d_in[2];
    const int*   users  = (const int*)d_in[3];
    const float* W_ih   = (const float*)d_in[4];
    const float* W_hh   = (const float*)d_in[5];
    const float* b_ih   = (const float*)d_in[6];
    const float* b_hh   = (const float*)d_in[7];
    const float* Wa     = (const float*)d_in[8];
    const float* ba     = (const float*)d_in[9];
    const float* Ws     = (const float*)d_in[10];
    // d_in[11] = bs: additive per-row constant on scores -> softmax-invariant.
    float* out = (float*)d_out;

    cudaFuncSetAttribute(k_xproj_mma, cudaFuncAttributeMaxDynamicSharedMemorySize,
                         XP_SMEM);
    cudaFuncSetAttribute(k_gru, cudaFuncAttributeMaxDynamicSharedMemorySize,
                         SMEM_GRU_BYTES);
    cudaFuncSetAttribute(k_attn_mma, cudaFuncAttributeMaxDynamicSharedMemorySize,
                         AT_SMEM);

    __nv_bfloat16 *xh, *xl, *wh, *wl, *wah, *wal;
    float* Cp;
    cudaGetSymbolAddress((void**)&xh, g_xh);
    cudaGetSymbolAddress((void**)&xl, g_xl);
    cudaGetSymbolAddress((void**)&wh, g_wh);
    cudaGetSymbolAddress((void**)&wl, g_wl);
    cudaGetSymbolAddress((void**)&wah, g_wah);
    cudaGetSymbolAddress((void**)&wal, g_wal);
    cudaGetSymbolAddress((void**)&Cp, g_C);

    const size_t nX  = (size_t)BB * SS * HH / 4;
    const size_t nW  = (size_t)GG * HH / 4;
    const size_t nWa = (size_t)NUSR * HH * HH / 4;
    k_split<<<(unsigned)((nX + 255) / 256), 256>>>(reps, xh, xl, nX);
    k_split<<<(unsigned)((nW + 255) / 256), 256>>>(W_ih, wh, wl, nW);
    k_split<<<(unsigned)((nWa + 255) / 256), 256>>>(Wa, wah, wal, nWa);
    k_colsum<<<dim3(NUSR, 64), 256>>>(Wa, Cp);

    dim3 g1(800, 6);
    k_xproj_mma<<<g1, 512, XP_SMEM>>>(b_ih);
    k_gru<<<BB / 8, 256, SMEM_GRU_BYTES>>>(hidden, W_hh, b_hh);
    k_attn_mma<<<BB, 256, AT_SMEM>>>(reps, counts, users, ba, Ws, out);
}

// round 9
// speedup vs baseline: 3.2809x; 2.7269x over previous
#include <cuda_runtime.h>
#include <cuda_bf16.h>
#include <math.h>
#include <stdint.h>

#define BB 1024
#define SS 100
#define HH 512
#define GG 1536   // 3*H
#define NUSR 1000

// ---------------------------------------------------------------------------
// Scratch (device globals: allowed; no runtime allocation)
// ---------------------------------------------------------------------------
__device__ float g_xproj[(size_t)BB * SS * GG];            // [B,S,3H] fp32
__device__ __nv_bfloat16 g_xh[(size_t)BB * SS * HH];       // X hi
__device__ __nv_bfloat16 g_xl[(size_t)BB * SS * HH];       // X lo
__device__ __nv_bfloat16 g_wh[(size_t)GG * HH];            // W_ih hi
__device__ __nv_bfloat16 g_wl[(size_t)GG * HH];            // W_ih lo
__device__ __nv_bfloat16 g_whhh[(size_t)GG * HH];          // W_hh hi
__device__ __nv_bfloat16 g_whhl[(size_t)GG * HH];          // W_hh lo
__device__ __nv_bfloat16 g_wah[(size_t)NUSR * HH * HH];    // Wa hi
__device__ __nv_bfloat16 g_wal[(size_t)NUSR * HH * HH];    // Wa lo
__device__ __nv_bfloat16 g_hh[(size_t)BB * 128 * HH];      // h for attention, hi (rows 100..127 stay 0)
__device__ __nv_bfloat16 g_hl[(size_t)BB * 128 * HH];      // h for attention, lo
__device__ __nv_bfloat16 g_hbh[(size_t)2 * BB * HH];       // h double buffer, hi
__device__ __nv_bfloat16 g_hbl[(size_t)2 * BB * HH];       // h double buffer, lo
__device__ float g_hstate[(size_t)BB * HH];                // exact fp32 h
__device__ float g_C[(size_t)NUSR * HH];                   // exact col-sums of Wa
__device__ unsigned g_bar[16];                             // spin barriers (memset each launch)

// ---------------------------------------------------------------------------
// Portable tensor-core primitives (compile for compute_103, no 'a' features)
// ---------------------------------------------------------------------------
__device__ __forceinline__ uint32_t smem_u32(const void* p) {
    uint32_t a;
    asm("{ .reg .u64 t; cvta.to.shared.u64 t, %1; cvt.u32.u64 %0, t; }"
        : "=r"(a) : "l"(p));
    return a;
}

#define CP_ASYNC16(sa, ga) \
    asm volatile("cp.async.cg.shared.global [%0], [%1], 16;" :: "r"(sa), "l"(ga))
#define CP_COMMIT() asm volatile("cp.async.commit_group;")
#define CP_WAIT1() asm volatile("cp.async.wait_group 1;" ::: "memory")
#define CP_WAIT0() asm volatile("cp.async.wait_group 0;" ::: "memory")

#define LDMX4(r0, r1, r2, r3, a) \
    asm volatile("ldmatrix.sync.aligned.m8n8.x4.shared.b16 {%0,%1,%2,%3}, [%4];" \
                 : "=r"(r0), "=r"(r1), "=r"(r2), "=r"(r3) : "r"(a))

#define LDMX2(r0, r1, a) \
    asm volatile("ldmatrix.sync.aligned.m8n8.x2.shared.b16 {%0,%1}, [%2];" \
                 : "=r"(r0), "=r"(r1) : "r"(a))

#define MMA_BF16(d, a, b) \
    asm volatile( \
        "mma.sync.aligned.m16n8k16.row.col.f32.bf16.bf16.f32 " \
        "{%0,%1,%2,%3}, {%4,%5,%6,%7}, {%8,%9}, {%0,%1,%2,%3};" \
        : "+f"((d)[0]), "+f"((d)[1]), "+f"((d)[2]), "+f"((d)[3]) \
        : "r"((a)[0]), "r"((a)[1]), "r"((a)[2]), "r"((a)[3]), \
          "r"((b)[0]), "r"((b)[1]))

// ---------------------------------------------------------------------------
// Kernel A: fp32 -> bf16 hi/lo split (generic, float4-granular)
// ---------------------------------------------------------------------------
__global__ void k_split(const float* __restrict__ src, __nv_bfloat16* __restrict__ hi,
                        __nv_bfloat16* __restrict__ lo, size_t n4) {
    size_t i = (size_t)blockIdx.x * 256 + threadIdx.x;
    if (i >= n4) return;
    float4 v = ((const float4*)src)[i];
    float f[4] = {v.x, v.y, v.z, v.w};
    union { __nv_bfloat16 h[4]; uint2 u; } H;
    union { __nv_bfloat16 h[4]; uint2 u; } L;
#pragma unroll
    for (int j = 0; j < 4; j++) {
        __nv_bfloat16 hh = __float2bfloat16(f[j]);
        H.h[j] = hh;
        L.h[j] = __float2bfloat16(f[j] - __bfloat162float(hh));
    }
    *(uint2*)(hi + i * 4) = H.u;
    *(uint2*)(lo + i * 4) = L.u;
}

// ---------------------------------------------------------------------------
// Kernel B: fused Wa split + exact fp32 column sums. One warp per (u,o) row.
// grid = NUSR*512/8 rows-of-8-warps, block 256.
// ---------------------------------------------------------------------------
__global__ void k_split_wa(const float* __restrict__ Wa, __nv_bfloat16* __restrict__ hi,
                           __nv_bfloat16* __restrict__ lo, float* __restrict__ C) {
    const size_t row = (size_t)blockIdx.x * 8 + (threadIdx.x >> 5);
    const int lane = threadIdx.x & 31;
    const float* src = Wa + row * 512;
    float s = 0.f;
#pragma unroll
    for (int q = 0; q < 4; q++) {
        int i = lane + q * 32;               // float4 index 0..127
        float4 v = ((const float4*)src)[i];
        float f[4] = {v.x, v.y, v.z, v.w};
        s += f[0] + f[1] + f[2] + f[3];
        union { __nv_bfloat16 h[4]; uint2 u; } H;
        union { __nv_bfloat16 h[4]; uint2 u; } L;
#pragma unroll
        for (int j = 0; j < 4; j++) {
            __nv_bfloat16 hh = __float2bfloat16(f[j]);
            H.h[j] = hh;
            L.h[j] = __float2bfloat16(f[j] - __bfloat162float(hh));
        }
        *(uint2*)(hi + row * 512 + i * 4) = H.u;
        *(uint2*)(lo + row * 512 + i * 4) = L.u;
    }
#pragma unroll
    for (int ofs = 16; ofs; ofs >>= 1) s += __shfl_xor_sync(0xffffffffu, s, ofs);
    if (lane == 0) C[row] = s;
}

// ---------------------------------------------------------------------------
// Kernel 1: x_proj = X @ W_ih^T + b_ih  via mma.sync bf16 split-3 (R8, works).
// ---------------------------------------------------------------------------
#define XP_AH 0
#define XP_AL 6144
#define XP_BH 12288
#define XP_BL 24576
#define XP_STG 36864
#define XP_SMEM (2 * XP_STG)

__global__ void __launch_bounds__(512, 1)
k_xproj_mma(const float* __restrict__ bias) {
    extern __shared__ char smx[];
    const uint32_t sb = smem_u32(smx);
    const int tid = threadIdx.x;
    const int wid = tid >> 5, lane = tid & 31;
    const int wm = wid >> 3, wn = wid & 7;
    const int bm = blockIdx.x;
    const int bn = blockIdx.y;
    const size_t m0 = (size_t)bm * 128;
    const size_t n0 = (size_t)bn * 256;

    const int ia  = tid & 255;
    const int ar  = ia >> 1, ac = ia & 1;
    const int br  = tid >> 1, bc = tid & 1;
    const bool isAl = (tid >= 256);

    float acc[4][4][4];
#pragma unroll
    for (int i = 0; i < 4; i++)
#pragma unroll
        for (int j = 0; j < 4; j++)
#pragma unroll
            for (int q = 0; q < 4; q++) acc[i][j][q] = 0.f;

    const uint32_t a_lane_off =
        (uint32_t)((wm * 64 + (lane & 15)) * 48 + (lane >> 4) * 16);
    const uint32_t b_lane_off =
        (uint32_t)((wn * 32 + (lane & 7) + (lane >> 4) * 8) * 48 +
                   ((lane >> 3) & 1) * 16);

    {
        uint32_t st = sb;
        const __nv_bfloat16* gA = isAl ? g_xl : g_xh;
        CP_ASYNC16(st + (isAl ? XP_AL : XP_AH) + ar * 48 + ac * 16,
                   gA + (m0 + ar) * 512 + ac * 8);
        CP_ASYNC16(st + XP_BH + br * 48 + bc * 16,
                   g_wh + (n0 + br) * 512 + bc * 8);
        CP_ASYNC16(st + XP_BL + br * 48 + bc * 16,
                   g_wl + (n0 + br) * 512 + bc * 8);
        CP_COMMIT();
    }

    for (int c = 0; c < 32; c++) {
        const uint32_t cur = sb + (uint32_t)(c & 1) * XP_STG;
        if (c < 31) {
            const int k0 = (c + 1) * 16;
            uint32_t st = sb + (uint32_t)((c + 1) & 1) * XP_STG;
            const __nv_bfloat16* gA = isAl ? g_xl : g_xh;
            CP_ASYNC16(st + (isAl ? XP_AL : XP_AH) + ar * 48 + ac * 16,
                       gA + (m0 + ar) * 512 + k0 + ac * 8);
            CP_ASYNC16(st + XP_BH + br * 48 + bc * 16,
                       g_wh + (n0 + br) * 512 + k0 + bc * 8);
            CP_ASYNC16(st + XP_BL + br * 48 + bc * 16,
                       g_wl + (n0 + br) * 512 + k0 + bc * 8);
            CP_COMMIT();
            CP_WAIT1();
        } else {
            CP_WAIT0();
        }
        __syncthreads();

        uint32_t bh[4][2], bl[4][2];
        {
            uint32_t r0, r1, r2, r3;
            LDMX4(r0, r1, r2, r3, cur + XP_BH + b_lane_off);
            bh[0][0] = r0; bh[0][1] = r1; bh[1][0] = r2; bh[1][1] = r3;
            LDMX4(r0, r1, r2, r3, cur + XP_BH + b_lane_off + 16 * 48);
            bh[2][0] = r0; bh[2][1] = r1; bh[3][0] = r2; bh[3][1] = r3;
            LDMX4(r0, r1, r2, r3, cur + XP_BL + b_lane_off);
            bl[0][0] = r0; bl[0][1] = r1; bl[1][0] = r2; bl[1][1] = r3;
            LDMX4(r0, r1, r2, r3, cur + XP_BL + b_lane_off + 16 * 48);
            bl[2][0] = r0; bl[2][1] = r1; bl[3][0] = r2; bl[3][1] = r3;
        }
#pragma unroll
        for (int mi = 0; mi < 4; mi++) {
            uint32_t ah[4], al[4];
            LDMX4(ah[0], ah[1], ah[2], ah[3], cur + XP_AH + a_lane_off + mi * 16 * 48);
            LDMX4(al[0], al[1], al[2], al[3], cur + XP_AL + a_lane_off + mi * 16 * 48);
#pragma unroll
            for (int nj = 0; nj < 4; nj++) {
                MMA_BF16(acc[mi][nj], ah, bh[nj]);
                MMA_BF16(acc[mi][nj], ah, bl[nj]);
                MMA_BF16(acc[mi][nj], al, bh[nj]);
            }
        }
        __syncthreads();
    }

    const int q = lane >> 2, cc = (lane & 3) * 2;
#pragma unroll
    for (int mi = 0; mi < 4; mi++) {
        const size_t r0 = m0 + wm * 64 + mi * 16 + q;
#pragma unroll
        for (int nj = 0; nj < 4; nj++) {
            const size_t nn = n0 + wn * 32 + nj * 8 + cc;
            float b0 = __ldg(bias + nn), b1 = __ldg(bias + nn + 1);
            float2 v0 = {acc[mi][nj][0] + b0, acc[mi][nj][1] + b1};
            float2 v1 = {acc[mi][nj][2] + b0, acc[mi][nj][3] + b1};
            *(float2*)(g_xproj + r0 * GG + nn) = v0;
            *(float2*)(g_xproj + (r0 + 8) * GG + nn) = v1;
        }
    }
}

// ---------------------------------------------------------------------------
// Kernel 2: persistent mma GRU.  Grid (16 n-slices, 8 m-tiles) = 128 CTAs,
// 1 CTA/SM guaranteed co-resident (smem 221KB).  Each CTA keeps its 96-row
// W_hh slice (gate-matched cols: rows {j,512+j,1024+j}) resident in SMEM as
// bf16 hi+lo, XOR-swizzled for conflict-free ldmatrix.  h exchanged via a
// double-buffered global bf16 hi/lo buffer + per-m-tile spin barrier.
// Per step: gh[128,96] = h[128,512] @ Wslice^T (split-3 mma), in-register
// gate epilogue (fp32, exact h state), write h hi/lo + attention copies.
// SMEM: Whi 96KB | Wlo 96KB | A stage 2 x (hi 6KB + lo 6KB) = 221,184 B.
// ---------------------------------------------------------------------------
#define GRU_WH 0
#define GRU_WL 98304
#define GRU_AST 196608
#define GRU_SMEM (196608 + 24576)

__global__ void __launch_bounds__(256, 1)
k_gru_mma(const float* __restrict__ h0, const float* __restrict__ bhh) {
    extern __shared__ char smx[];
    const uint32_t sb = smem_u32(smx);
    const int tid = threadIdx.x;
    const int wid = tid >> 5, lane = tid & 31;
    const int wm = wid >> 2, wn = wid & 3;     // 2 x 4 warps: M 64, 8 h-cols
    const int ns = blockIdx.x;                 // 0..15  (32 h-cols each)
    const int mt = blockIdx.y;                 // 0..7   (128 batch rows each)
    const int cid = mt * 16 + ns;
    const int mrow0 = mt * 128;

    // ---- prologue: W slice -> swizzled SMEM (cp.async) ----
#pragma unroll
    for (int qq = 0; qq < 24; qq++) {
        int gi = tid + 256 * qq;               // 6144 granules
        int lr = gi >> 6, g16 = gi & 63;
        int grow = (lr >> 5) * 512 + ns * 32 + (lr & 31);
        uint32_t phys = (uint32_t)lr * 1024 + (uint32_t)((g16 ^ (lr & 7)) << 4);
        CP_ASYNC16(sb + GRU_WH + phys, g_whhh + (size_t)grow * 512 + g16 * 8);
        CP_ASYNC16(sb + GRU_WL + phys, g_whhl + (size_t)grow * 512 + g16 * 8);
    }
    CP_COMMIT();

    // ---- prologue: h0 -> hstate + h_buf[0] (rows cid*8..+8) ----
#pragma unroll
    for (int qq = 0; qq < 4; qq++) {
        int idx = tid + 256 * qq;              // 1024 float4 = 8*512/4
        int r = idx >> 7, cp4 = (idx & 127) * 4;
        size_t o = (size_t)(cid * 8 + r) * 512 + cp4;
        float4 v = *(const float4*)(h0 + o);
        *(float4*)(g_hstate + o) = v;
        float f[4] = {v.x, v.y, v.z, v.w};
        union { __nv_bfloat16 h[4]; uint2 u; } H;
        union { __nv_bfloat16 h[4]; uint2 u; } L;
#pragma unroll
        for (int j = 0; j < 4; j++) {
            __nv_bfloat16 hh = __float2bfloat16(f[j]);
            H.h[j] = hh;
            L.h[j] = __float2bfloat16(f[j] - __bfloat162float(hh));
        }
        *(uint2*)(g_hbh + o) = H.u;
        *(uint2*)(g_hbl + o) = L.u;
    }
    __threadfence();
    __syncthreads();
    if (tid == 0) {
        atomicAdd(&g_bar[8], 1u);
        volatile unsigned* p = &g_bar[8];
        while (*p < 128u) {}
    }
    __syncthreads();
    __threadfence();
    CP_WAIT0();
    __syncthreads();

    // ---- per-thread constants ----
    const int ar = tid >> 1, ahf = tid & 1;    // A-stage cp.async (128 rows x 2)
    const uint32_t a_base =
        (uint32_t)((wm * 64 + (lane & 15)) * 48 + (lane >> 4) * 16);
    int lrB[3];
#pragma unroll
    for (int g = 0; g < 3; g++) lrB[g] = g * 32 + wn * 8 + (lane & 7);
    const int kbit = (lane >> 3) & 1;
    const int qrow = lane >> 2, cc = (lane & 3) * 2;
    const int c0 = ns * 32 + wn * 8 + cc;      // h-col of acc pair
    float bhg[3][2];
#pragma unroll
    for (int g = 0; g < 3; g++) {
        bhg[g][0] = __ldg(bhh + g * 512 + c0);
        bhg[g][1] = __ldg(bhh + g * 512 + c0 + 1);
    }

    unsigned bar_target = 16;
    for (int t = 0; t < SS; t++) {
        const int cur = t & 1, nxt = cur ^ 1;
        const __nv_bfloat16* hb = g_hbh + (size_t)cur * (BB * HH);
        const __nv_bfloat16* hl = g_hbl + (size_t)cur * (BB * HH);

        // issue A chunk 0
        {
            uint32_t st = sb + GRU_AST;
            CP_ASYNC16(st + ar * 48 + ahf * 16,
                       hb + (size_t)(mrow0 + ar) * 512 + ahf * 8);
            CP_ASYNC16(st + 6144 + ar * 48 + ahf * 16,
                       hl + (size_t)(mrow0 + ar) * 512 + ahf * 8);
            CP_COMMIT();
        }

        float acc[4][3][4];
#pragma unroll
        for (int i = 0; i < 4; i++)
#pragma unroll
            for (int g = 0; g < 3; g++)
#pragma unroll
                for (int z = 0; z < 4; z++) acc[i][g][z] = 0.f;

        for (int c = 0; c < 32; c++) {
            CP_WAIT0();
            __syncthreads();
            if (c < 31) {
                uint32_t st = sb + GRU_AST + (uint32_t)((c + 1) & 1) * 12288;
                const int kb = (c + 1) * 16 + ahf * 8;
                CP_ASYNC16(st + ar * 48 + ahf * 16,
                           hb + (size_t)(mrow0 + ar) * 512 + kb);
                CP_ASYNC16(st + 6144 + ar * 48 + ahf * 16,
                           hl + (size_t)(mrow0 + ar) * 512 + kb);
                CP_COMMIT();
            }
            const uint32_t cs = sb + GRU_AST + (uint32_t)(c & 1) * 12288;

            uint32_t bhf[3][2], blf[3][2];
#pragma unroll
            for (int g = 0; g < 3; g++) {
                int g16 = 2 * c + kbit;
                uint32_t phys = (uint32_t)lrB[g] * 1024 +
                                (uint32_t)((g16 ^ (lrB[g] & 7)) << 4);
                LDMX2(bhf[g][0], bhf[g][1], sb + GRU_WH + phys);
                LDMX2(blf[g][0], blf[g][1], sb + GRU_WL + phys);
            }
#pragma unroll
            for (int mi = 0; mi < 4; mi++) {
                uint32_t ah[4], al[4];
                LDMX4(ah[0], ah[1], ah[2], ah[3], cs + a_base + mi * 768);
                LDMX4(al[0], al[1], al[2], al[3], cs + 6144 + a_base + mi * 768);
#pragma unroll
                for (int g = 0; g < 3; g++) {
                    MMA_BF16(acc[mi][g], ah, bhf[g]);
                    MMA_BF16(acc[mi][g], ah, blf[g]);
                    MMA_BF16(acc[mi][g], al, bhf[g]);
                }
            }
        }
        __syncthreads();

        // ---- in-register gate epilogue ----
#pragma unroll
        for (int mi = 0; mi < 4; mi++) {
#pragma unroll
            for (int hp = 0; hp < 2; hp++) {
                const int b = mrow0 + wm * 64 + mi * 16 + qrow + hp * 8;
                const size_t xb = ((size_t)b * SS + t) * GG + c0;
                float xr0 = g_xproj[xb],        xr1 = g_xproj[xb + 1];
                float xz0 = g_xproj[xb + 512],  xz1 = g_xproj[xb + 513];
                float xn0 = g_xproj[xb + 1024], xn1 = g_xproj[xb + 1025];
                float2 hold = *(const float2*)(g_hstate + (size_t)b * 512 + c0);
                float hr0 = acc[mi][0][hp * 2 + 0] + bhg[0][0];
                float hr1 = acc[mi][0][hp * 2 + 1] + bhg[0][1];
                float hz0 = acc[mi][1][hp * 2 + 0] + bhg[1][0];
                float hz1 = acc[mi][1][hp * 2 + 1] + bhg[1][1];
                float hn0 = acc[mi][2][hp * 2 + 0] + bhg[2][0];
                float hn1 = acc[mi][2][hp * 2 + 1] + bhg[2][1];
                float rg0 = 1.f / (1.f + expf(-(xr0 + hr0)));
                float rg1 = 1.f / (1.f + expf(-(xr1 + hr1)));
                float zg0 = 1.f / (1.f + expf(-(xz0 + hz0)));
                float zg1 = 1.f / (1.f + expf(-(xz1 + hz1)));
                float ng0 = tanhf(xn0 + rg0 * hn0);
                float ng1 = tanhf(xn1 + rg1 * hn1);
                float h0n = (1.f - zg0) * ng0 + zg0 * hold.x;
                float h1n = (1.f - zg1) * ng1 + zg1 * hold.y;
                float2 hsv = {h0n, h1n};
                *(float2*)(g_hstate + (size_t)b * 512 + c0) = hsv;
                __nv_bfloat16 p0 = __float2bfloat16(h0n);
                __nv_bfloat16 p1 = __float2bfloat16(h1n);
                __nv_bfloat16 q0 = __float2bfloat16(h0n - __bfloat162float(p0));
                __nv_bfloat16 q1 = __float2bfloat16(h1n - __bfloat162float(p1));
                __nv_bfloat162 ph = __halves2bfloat162(p0, p1);
                __nv_bfloat162 pl = __halves2bfloat162(q0, q1);
                size_t ob = (size_t)nxt * (BB * HH) + (size_t)b * 512 + c0;
                *(__nv_bfloat162*)(g_hbh + ob) = ph;
                *(__nv_bfloat162*)(g_hbl + ob) = pl;
                size_t oa = ((size_t)b * 128 + t) * 512 + c0;
                *(__nv_bfloat162*)(g_hh + oa) = ph;
                *(__nv_bfloat162*)(g_hl + oa) = pl;
            }
        }
        __threadfence();
        __syncthreads();
        if (tid == 0) {
            atomicAdd(&g_bar[mt], 1u);
            volatile unsigned* p = &g_bar[mt];
            while (*p < bar_target) {}
        }
        __syncthreads();
        __threadfence();
        bar_target += 16;
    }
}

// ---------------------------------------------------------------------------
// Kernel 3: attention via mma.sync (R8, works). One CTA per b.
// ---------------------------------------------------------------------------
#define AT_BASE 7168
#define AT_AH 0
#define AT_AL 6144
#define AT_BH 12288
#define AT_BL 18432
#define AT_STG 24576
#define AT_SMEM (AT_BASE + 2 * AT_STG)

__global__ void __launch_bounds__(256, 1)
k_attn_mma(const float* __restrict__ reps, const int* __restrict__ counts,
           const int* __restrict__ users, const float* __restrict__ ba,
           const float* __restrict__ Wsv, float* __restrict__ outp) {
    extern __shared__ char smx[];
    const uint32_t sb = smem_u32(smx);
    float* ba_s  = (float*)(smx);
    float* ws_s  = (float*)(smx + 2048);
    float* C_s   = (float*)(smx + 4096);
    float* score = (float*)(smx + 6144);
    const int tid = threadIdx.x;
    const int wid = tid >> 5, lane = tid & 31;
    const int wm = wid >> 2, wn = wid & 3;
    const int b = blockIdx.x;
    const int cnt = counts[b];
    const int u = users[b];

    ba_s[tid]       = ba[(size_t)u * 512 + tid];
    ba_s[tid + 256] = ba[(size_t)u * 512 + 256 + tid];
    ws_s[tid]       = Wsv[(size_t)u * 512 + tid];
    ws_s[tid + 256] = Wsv[(size_t)u * 512 + 256 + tid];
    C_s[tid]        = g_C[(size_t)u * 512 + tid];
    C_s[tid + 256]  = g_C[(size_t)u * 512 + 256 + tid];
    if (tid < 128) score[tid] = 0.f;
    __syncthreads();

    const __nv_bfloat16* Ahg = g_hh + (size_t)b * 128 * 512;
    const __nv_bfloat16* Alg = g_hl + (size_t)b * 128 * 512;
    const __nv_bfloat16* Bhg = g_wah + (size_t)u * 512 * 512;
    const __nv_bfloat16* Blg = g_wal + (size_t)u * 512 * 512;

    const int tr = tid >> 1, tc = tid & 1;
    const uint32_t a_lane_off =
        (uint32_t)((wm * 64 + (lane & 15)) * 48 + (lane >> 4) * 16);
    const uint32_t b_lane_off =
        (uint32_t)((wn * 32 + (lane & 7) + (lane >> 4) * 8) * 48 +
                   ((lane >> 3) & 1) * 16);
    const int q = lane >> 2, cc = (lane & 3) * 2;

    {
        uint32_t st = sb + AT_BASE;
        CP_ASYNC16(st + AT_AH + tr * 48 + tc * 16, Ahg + tr * 512 + tc * 8);
        CP_ASYNC16(st + AT_AL + tr * 48 + tc * 16, Alg + tr * 512 + tc * 8);
        CP_ASYNC16(st + AT_BH + tr * 48 + tc * 16, Bhg + tr * 512 + tc * 8);
        CP_ASYNC16(st + AT_BL + tr * 48 + tc * 16, Blg + tr * 512 + tc * 8);
        CP_COMMIT();
    }

    float acc[4][4][4];
    for (int it = 0; it < 128; it++) {
        const int np = it >> 5, c = it & 31;
        if (c == 0) {
#pragma unroll
            for (int i = 0; i < 4; i++)
#pragma unroll
                for (int j = 0; j < 4; j++)
#pragma unroll
                    for (int z = 0; z < 4; z++) acc[i][j][z] = 0.f;
        }
        const uint32_t cur = sb + AT_BASE + (uint32_t)(it & 1) * AT_STG;
        if (it < 127) {
            const int np2 = (it + 1) >> 5, c2 = (it + 1) & 31;
            const int k0 = c2 * 16;
            uint32_t st = sb + AT_BASE + (uint32_t)((it + 1) & 1) * AT_STG;
            CP_ASYNC16(st + AT_AH + tr * 48 + tc * 16,
                       Ahg + tr * 512 + k0 + tc * 8);
            CP_ASYNC16(st + AT_AL + tr * 48 + tc * 16,
                       Alg + tr * 512 + k0 + tc * 8);
            CP_ASYNC16(st + AT_BH + tr * 48 + tc * 16,
                       Bhg + (size_t)(np2 * 128 + tr) * 512 + k0 + tc * 8);
            CP_ASYNC16(st + AT_BL + tr * 48 + tc * 16,
                       Blg + (size_t)(np2 * 128 + tr) * 512 + k0 + tc * 8);
            CP_COMMIT();
            CP_WAIT1();
        } else {
            CP_WAIT0();
        }
        __syncthreads();

        uint32_t bh[4][2], bl[4][2];
        {
            uint32_t r0, r1, r2, r3;
            LDMX4(r0, r1, r2, r3, cur + AT_BH + b_lane_off);
            bh[0][0] = r0; bh[0][1] = r1; bh[1][0] = r2; bh[1][1] = r3;
            LDMX4(r0, r1, r2, r3, cur + AT_BH + b_lane_off + 16 * 48);
            bh[2][0] = r0; bh[2][1] = r1; bh[3][0] = r2; bh[3][1] = r3;
            LDMX4(r0, r1, r2, r3, cur + AT_BL + b_lane_off);
            bl[0][0] = r0; bl[0][1] = r1; bl[1][0] = r2; bl[1][1] = r3;
            LDMX4(r0, r1, r2, r3, cur + AT_BL + b_lane_off + 16 * 48);
            bl[2][0] = r0; bl[2][1] = r1; bl[3][0] = r2; bl[3][1] = r3;
        }
#pragma unroll
        for (int mi = 0; mi < 4; mi++) {
            uint32_t ah[4], al[4];
            LDMX4(ah[0], ah[1], ah[2], ah[3], cur + AT_AH + a_lane_off + mi * 16 * 48);
            LDMX4(al[0], al[1], al[2], al[3], cur + AT_AL + a_lane_off + mi * 16 * 48);
#pragma unroll
            for (int nj = 0; nj < 4; nj++) {
                MMA_BF16(acc[mi][nj], ah, bh[nj]);
                MMA_BF16(acc[mi][nj], ah, bl[nj]);
                MMA_BF16(acc[mi][nj], al, bh[nj]);
            }
        }
        __syncthreads();

        if (c == 31) {
#pragma unroll
            for (int mi = 0; mi < 4; mi++) {
                const int s0 = wm * 64 + mi * 16 + q;
#pragma unroll
                for (int half = 0; half < 2; half++) {
                    const int s = s0 + half * 8;
                    const bool valid = (s < 100);
                    const float msk = (valid && s >= cnt) ? 1000000.0f : 0.0f;
                    float psum = 0.f;
#pragma unroll
                    for (int nj = 0; nj < 4; nj++) {
                        const int o0 = np * 128 + wn * 32 + nj * 8 + cc;
                        float a0 = acc[mi][nj][half * 2 + 0] + ba_s[o0] - msk * C_s[o0];
                        float a1 = acc[mi][nj][half * 2 + 1] + ba_s[o0 + 1] - msk * C_s[o0 + 1];
                        psum += ws_s[o0] * tanhf(a0) + ws_s[o0 + 1] * tanhf(a1);
                    }
                    psum += __shfl_xor_sync(0xffffffffu, psum, 1);
                    psum += __shfl_xor_sync(0xffffffffu, psum, 2);
                    if ((lane & 3) == 0 && valid) atomicAdd(&score[s], psum);
                }
            }
        }
    }
    __syncthreads();

    if (tid < 32) {
        float mx = -1e30f;
        for (int s = tid; s < 100; s += 32) mx = fmaxf(mx, score[s]);
#pragma unroll
        for (int o = 16; o > 0; o >>= 1) mx = fmaxf(mx, __shfl_xor_sync(0xffffffffu, mx, o));
        float ssum = 0.f;
        for (int s = tid; s < 100; s += 32) {
            float e = expf(score[s] - mx);
            score[s] = e;
            ssum += e;
        }
#pragma unroll
        for (int o = 16; o > 0; o >>= 1) ssum += __shfl_xor_sync(0xffffffffu, ssum, o);
        float inv = 1.f / ssum;
        for (int s = tid; s < 100; s += 32) score[s] *= inv;
    }
    __syncthreads();

    const float* rb = reps + (size_t)b * (SS * HH);
    for (int h = tid; h < 512; h += 256) {
        float a0 = 0.f;
        for (int s = 0; s < 100; s++) a0 += score[s] * rb[s * 512 + h];
        outp[(size_t)b * 512 + h] = a0;
    }
}

// ---------------------------------------------------------------------------
extern "C" void kernel_launch(void* const* d_in, const int* in_sizes, int n_in,
                              void* d_out, int out_size) {
    const float* reps   = (const float*)d_in[0];
    const float* hidden = (const float*)d_in[1];
    const int*   counts = (const int*)d_in[2];
    const int*   users  = (const int*)d_in[3];
    const float* W_ih   = (const float*)d_in[4];
    const float* W_hh   = (const float*)d_in[5];
    const float* b_ih   = (const float*)d_in[6];
    const float* b_hh   = (const float*)d_in[7];
    const float* Wa     = (const float*)d_in[8];
    const float* ba     = (const float*)d_in[9];
    const float* Ws     = (const float*)d_in[10];
    // d_in[11] = bs: additive per-row constant on scores -> softmax-invariant.
    float* out = (float*)d_out;

    cudaFuncSetAttribute(k_xproj_mma, cudaFuncAttributeMaxDynamicSharedMemorySize,
                         XP_SMEM);
    cudaFuncSetAttribute(k_gru_mma, cudaFuncAttributeMaxDynamicSharedMemorySize,
                         GRU_SMEM);
    cudaFuncSetAttribute(k_attn_mma, cudaFuncAttributeMaxDynamicSharedMemorySize,
                         AT_SMEM);

    __nv_bfloat16 *xh, *xl, *wh, *wl, *whhh, *whhl, *wah, *wal;
    float* Cp;
    void* barp;
    cudaGetSymbolAddress((void**)&xh, g_xh);
    cudaGetSymbolAddress((void**)&xl, g_xl);
    cudaGetSymbolAddress((void**)&wh, g_wh);
    cudaGetSymbolAddress((void**)&wl, g_wl);
    cudaGetSymbolAddress((void**)&whhh, g_whhh);
    cudaGetSymbolAddress((void**)&whhl, g_whhl);
    cudaGetSymbolAddress((void**)&wah, g_wah);
    cudaGetSymbolAddress((void**)&wal, g_wal);
    cudaGetSymbolAddress((void**)&Cp, g_C);
    cudaGetSymbolAddress(&barp, g_bar);

    cudaMemsetAsync(barp, 0, 16 * sizeof(unsigned));

    const size_t nX  = (size_t)BB * SS * HH / 4;
    const size_t nW  = (size_t)GG * HH / 4;
    k_split<<<(unsigned)((nX + 255) / 256), 256>>>(reps, xh, xl, nX);
    k_split<<<(unsigned)((nW + 255) / 256), 256>>>(W_ih, wh, wl, nW);
    k_split<<<(unsigned)((nW + 255) / 256), 256>>>(W_hh, whhh, whhl, nW);
    k_split_wa<<<(unsigned)(NUSR * HH / 8), 256>>>(Wa, wah, wal, Cp);

    dim3 g1(800, 6);
    k_xproj_mma<<<g1, 512, XP_SMEM>>>(b_ih);
    k_gru_mma<<<dim3(16, 8), 256, GRU_SMEM>>>(hidden, b_hh);
    k_attn_mma<<<BB, 256, AT_SMEM>>>(reps, counts, users, ba, Ws, out);
}

// round 10
// speedup vs baseline: 3.4495x; 1.0514x over previous
#include <cuda_runtime.h>
#include <cuda_bf16.h>
#include <math.h>
#include <stdint.h>

#define BB 1024
#define SS 100
#define HH 512
#define GG 1536   // 3*H
#define NUSR 1000

// ---------------------------------------------------------------------------
// Scratch (device globals: allowed; no runtime allocation)
// ---------------------------------------------------------------------------
__device__ float g_xproj[(size_t)BB * SS * GG];            // [B,S,3H] fp32
__device__ __nv_bfloat16 g_xh[(size_t)BB * SS * HH];       // X hi
__device__ __nv_bfloat16 g_xl[(size_t)BB * SS * HH];       // X lo
__device__ __nv_bfloat16 g_wh[(size_t)GG * HH];            // W_ih hi
__device__ __nv_bfloat16 g_wl[(size_t)GG * HH];            // W_ih lo
__device__ __nv_bfloat16 g_whhh[(size_t)GG * HH];          // W_hh hi
__device__ __nv_bfloat16 g_whhl[(size_t)GG * HH];          // W_hh lo
__device__ __nv_bfloat16 g_hh[(size_t)BB * 128 * HH];      // h for attention, hi (rows 100..127 stay 0)
__device__ __nv_bfloat16 g_hl[(size_t)BB * 128 * HH];      // h for attention, lo
__device__ __nv_bfloat16 g_hbh[(size_t)2 * BB * HH];       // h double buffer, hi
__device__ __nv_bfloat16 g_hbl[(size_t)2 * BB * HH];       // h double buffer, lo
__device__ float g_hstate[(size_t)BB * HH];                // exact fp32 h
__device__ unsigned g_bar[16];                             // spin barriers (memset each launch)

// ---------------------------------------------------------------------------
// Portable tensor-core primitives (compile for compute_103, no 'a' features)
// ---------------------------------------------------------------------------
__device__ __forceinline__ uint32_t smem_u32(const void* p) {
    uint32_t a;
    asm("{ .reg .u64 t; cvta.to.shared.u64 t, %1; cvt.u32.u64 %0, t; }"
        : "=r"(a) : "l"(p));
    return a;
}

#define CP_ASYNC16(sa, ga) \
    asm volatile("cp.async.cg.shared.global [%0], [%1], 16;" :: "r"(sa), "l"(ga))
#define CP_COMMIT() asm volatile("cp.async.commit_group;")
#define CP_WAIT1() asm volatile("cp.async.wait_group 1;" ::: "memory")
#define CP_WAIT0() asm volatile("cp.async.wait_group 0;" ::: "memory")

#define LDMX4(r0, r1, r2, r3, a) \
    asm volatile("ldmatrix.sync.aligned.m8n8.x4.shared.b16 {%0,%1,%2,%3}, [%4];" \
                 : "=r"(r0), "=r"(r1), "=r"(r2), "=r"(r3) : "r"(a))

#define LDMX2(r0, r1, a) \
    asm volatile("ldmatrix.sync.aligned.m8n8.x2.shared.b16 {%0,%1}, [%2];" \
                 : "=r"(r0), "=r"(r1) : "r"(a))

#define MMA_BF16(d, a, b) \
    asm volatile( \
        "mma.sync.aligned.m16n8k16.row.col.f32.bf16.bf16.f32 " \
        "{%0,%1,%2,%3}, {%4,%5,%6,%7}, {%8,%9}, {%0,%1,%2,%3};" \
        : "+f"((d)[0]), "+f"((d)[1]), "+f"((d)[2]), "+f"((d)[3]) \
        : "r"((a)[0]), "r"((a)[1]), "r"((a)[2]), "r"((a)[3]), \
          "r"((b)[0]), "r"((b)[1]))

// fp32 -> bf16 hi/lo split of 8 values, packed as uint4 each
__device__ __forceinline__ void cvt8(const float* f, uint4& hv, uint4& lv) {
    union { __nv_bfloat16 h[8]; uint4 u; } H;
    union { __nv_bfloat16 h[8]; uint4 u; } L;
#pragma unroll
    for (int j = 0; j < 8; j++) {
        __nv_bfloat16 hh = __float2bfloat16(f[j]);
        H.h[j] = hh;
        L.h[j] = __float2bfloat16(f[j] - __bfloat162float(hh));
    }
    hv = H.u; lv = L.u;
}

// ---------------------------------------------------------------------------
// Kernel A: fp32 -> bf16 hi/lo split (generic, float4-granular)
// ---------------------------------------------------------------------------
__global__ void k_split(const float* __restrict__ src, __nv_bfloat16* __restrict__ hi,
                        __nv_bfloat16* __restrict__ lo, size_t n4) {
    size_t i = (size_t)blockIdx.x * 256 + threadIdx.x;
    if (i >= n4) return;
    float4 v = ((const float4*)src)[i];
    float f[4] = {v.x, v.y, v.z, v.w};
    union { __nv_bfloat16 h[4]; uint2 u; } H;
    union { __nv_bfloat16 h[4]; uint2 u; } L;
#pragma unroll
    for (int j = 0; j < 4; j++) {
        __nv_bfloat16 hh = __float2bfloat16(f[j]);
        H.h[j] = hh;
        L.h[j] = __float2bfloat16(f[j] - __bfloat162float(hh));
    }
    *(uint2*)(hi + i * 4) = H.u;
    *(uint2*)(lo + i * 4) = L.u;
}

// ---------------------------------------------------------------------------
// Kernel 1: x_proj = X @ W_ih^T + b_ih  via mma.sync bf16 split-3 (R8, works).
// ---------------------------------------------------------------------------
#define XP_AH 0
#define XP_AL 6144
#define XP_BH 12288
#define XP_BL 24576
#define XP_STG 36864
#define XP_SMEM (2 * XP_STG)

__global__ void __launch_bounds__(512, 1)
k_xproj_mma(const float* __restrict__ bias) {
    extern __shared__ char smx[];
    const uint32_t sb = smem_u32(smx);
    const int tid = threadIdx.x;
    const int wid = tid >> 5, lane = tid & 31;
    const int wm = wid >> 3, wn = wid & 7;
    const int bm = blockIdx.x;
    const int bn = blockIdx.y;
    const size_t m0 = (size_t)bm * 128;
    const size_t n0 = (size_t)bn * 256;

    const int ia  = tid & 255;
    const int ar  = ia >> 1, ac = ia & 1;
    const int br  = tid >> 1, bc = tid & 1;
    const bool isAl = (tid >= 256);

    float acc[4][4][4];
#pragma unroll
    for (int i = 0; i < 4; i++)
#pragma unroll
        for (int j = 0; j < 4; j++)
#pragma unroll
            for (int q = 0; q < 4; q++) acc[i][j][q] = 0.f;

    const uint32_t a_lane_off =
        (uint32_t)((wm * 64 + (lane & 15)) * 48 + (lane >> 4) * 16);
    const uint32_t b_lane_off =
        (uint32_t)((wn * 32 + (lane & 7) + (lane >> 4) * 8) * 48 +
                   ((lane >> 3) & 1) * 16);

    {
        uint32_t st = sb;
        const __nv_bfloat16* gA = isAl ? g_xl : g_xh;
        CP_ASYNC16(st + (isAl ? XP_AL : XP_AH) + ar * 48 + ac * 16,
                   gA + (m0 + ar) * 512 + ac * 8);
        CP_ASYNC16(st + XP_BH + br * 48 + bc * 16,
                   g_wh + (n0 + br) * 512 + bc * 8);
        CP_ASYNC16(st + XP_BL + br * 48 + bc * 16,
                   g_wl + (n0 + br) * 512 + bc * 8);
        CP_COMMIT();
    }

    for (int c = 0; c < 32; c++) {
        const uint32_t cur = sb + (uint32_t)(c & 1) * XP_STG;
        if (c < 31) {
            const int k0 = (c + 1) * 16;
            uint32_t st = sb + (uint32_t)((c + 1) & 1) * XP_STG;
            const __nv_bfloat16* gA = isAl ? g_xl : g_xh;
            CP_ASYNC16(st + (isAl ? XP_AL : XP_AH) + ar * 48 + ac * 16,
                       gA + (m0 + ar) * 512 + k0 + ac * 8);
            CP_ASYNC16(st + XP_BH + br * 48 + bc * 16,
                       g_wh + (n0 + br) * 512 + k0 + bc * 8);
            CP_ASYNC16(st + XP_BL + br * 48 + bc * 16,
                       g_wl + (n0 + br) * 512 + k0 + bc * 8);
            CP_COMMIT();
            CP_WAIT1();
        } else {
            CP_WAIT0();
        }
        __syncthreads();

        uint32_t bh[4][2], bl[4][2];
        {
            uint32_t r0, r1, r2, r3;
            LDMX4(r0, r1, r2, r3, cur + XP_BH + b_lane_off);
            bh[0][0] = r0; bh[0][1] = r1; bh[1][0] = r2; bh[1][1] = r3;
            LDMX4(r0, r1, r2, r3, cur + XP_BH + b_lane_off + 16 * 48);
            bh[2][0] = r0; bh[2][1] = r1; bh[3][0] = r2; bh[3][1] = r3;
            LDMX4(r0, r1, r2, r3, cur + XP_BL + b_lane_off);
            bl[0][0] = r0; bl[0][1] = r1; bl[1][0] = r2; bl[1][1] = r3;
            LDMX4(r0, r1, r2, r3, cur + XP_BL + b_lane_off + 16 * 48);
            bl[2][0] = r0; bl[2][1] = r1; bl[3][0] = r2; bl[3][1] = r3;
        }
#pragma unroll
        for (int mi = 0; mi < 4; mi++) {
            uint32_t ah[4], al[4];
            LDMX4(ah[0], ah[1], ah[2], ah[3], cur + XP_AH + a_lane_off + mi * 16 * 48);
            LDMX4(al[0], al[1], al[2], al[3], cur + XP_AL + a_lane_off + mi * 16 * 48);
#pragma unroll
            for (int nj = 0; nj < 4; nj++) {
                MMA_BF16(acc[mi][nj], ah, bh[nj]);
                MMA_BF16(acc[mi][nj], ah, bl[nj]);
                MMA_BF16(acc[mi][nj], al, bh[nj]);
            }
        }
        __syncthreads();
    }

    const int q = lane >> 2, cc = (lane & 3) * 2;
#pragma unroll
    for (int mi = 0; mi < 4; mi++) {
        const size_t r0 = m0 + wm * 64 + mi * 16 + q;
#pragma unroll
        for (int nj = 0; nj < 4; nj++) {
            const size_t nn = n0 + wn * 32 + nj * 8 + cc;
            float b0 = __ldg(bias + nn), b1 = __ldg(bias + nn + 1);
            float2 v0 = {acc[mi][nj][0] + b0, acc[mi][nj][1] + b1};
            float2 v1 = {acc[mi][nj][2] + b0, acc[mi][nj][3] + b1};
            *(float2*)(g_xproj + r0 * GG + nn) = v0;
            *(float2*)(g_xproj + (r0 + 8) * GG + nn) = v1;
        }
    }
}

// ---------------------------------------------------------------------------
// Kernel 2: persistent mma GRU (R9, works).  128 CTAs, W_hh slice resident in
// SMEM, h exchanged via global double buffer + per-m-tile spin barrier.
// ---------------------------------------------------------------------------
#define GRU_WH 0
#define GRU_WL 98304
#define GRU_AST 196608
#define GRU_SMEM (196608 + 24576)

__global__ void __launch_bounds__(256, 1)
k_gru_mma(const float* __restrict__ h0, const float* __restrict__ bhh) {
    extern __shared__ char smx[];
    const uint32_t sb = smem_u32(smx);
    const int tid = threadIdx.x;
    const int wid = tid >> 5, lane = tid & 31;
    const int wm = wid >> 2, wn = wid & 3;
    const int ns = blockIdx.x;
    const int mt = blockIdx.y;
    const int cid = mt * 16 + ns;
    const int mrow0 = mt * 128;

#pragma unroll
    for (int qq = 0; qq < 24; qq++) {
        int gi = tid + 256 * qq;
        int lr = gi >> 6, g16 = gi & 63;
        int grow = (lr >> 5) * 512 + ns * 32 + (lr & 31);
        uint32_t phys = (uint32_t)lr * 1024 + (uint32_t)((g16 ^ (lr & 7)) << 4);
        CP_ASYNC16(sb + GRU_WH + phys, g_whhh + (size_t)grow * 512 + g16 * 8);
        CP_ASYNC16(sb + GRU_WL + phys, g_whhl + (size_t)grow * 512 + g16 * 8);
    }
    CP_COMMIT();

#pragma unroll
    for (int qq = 0; qq < 4; qq++) {
        int idx = tid + 256 * qq;
        int r = idx >> 7, cp4 = (idx & 127) * 4;
        size_t o = (size_t)(cid * 8 + r) * 512 + cp4;
        float4 v = *(const float4*)(h0 + o);
        *(float4*)(g_hstate + o) = v;
        float f[4] = {v.x, v.y, v.z, v.w};
        union { __nv_bfloat16 h[4]; uint2 u; } H;
        union { __nv_bfloat16 h[4]; uint2 u; } L;
#pragma unroll
        for (int j = 0; j < 4; j++) {
            __nv_bfloat16 hh = __float2bfloat16(f[j]);
            H.h[j] = hh;
            L.h[j] = __float2bfloat16(f[j] - __bfloat162float(hh));
        }
        *(uint2*)(g_hbh + o) = H.u;
        *(uint2*)(g_hbl + o) = L.u;
    }
    __threadfence();
    __syncthreads();
    if (tid == 0) {
        atomicAdd(&g_bar[8], 1u);
        volatile unsigned* p = &g_bar[8];
        while (*p < 128u) {}
    }
    __syncthreads();
    __threadfence();
    CP_WAIT0();
    __syncthreads();

    const int ar = tid >> 1, ahf = tid & 1;
    const uint32_t a_base =
        (uint32_t)((wm * 64 + (lane & 15)) * 48 + (lane >> 4) * 16);
    int lrB[3];
#pragma unroll
    for (int g = 0; g < 3; g++) lrB[g] = g * 32 + wn * 8 + (lane & 7);
    const int kbit = (lane >> 3) & 1;
    const int qrow = lane >> 2, cc = (lane & 3) * 2;
    const int c0 = ns * 32 + wn * 8 + cc;
    float bhg[3][2];
#pragma unroll
    for (int g = 0; g < 3; g++) {
        bhg[g][0] = __ldg(bhh + g * 512 + c0);
        bhg[g][1] = __ldg(bhh + g * 512 + c0 + 1);
    }

    unsigned bar_target = 16;
    for (int t = 0; t < SS; t++) {
        const int cur = t & 1, nxt = cur ^ 1;
        const __nv_bfloat16* hb = g_hbh + (size_t)cur * (BB * HH);
        const __nv_bfloat16* hl = g_hbl + (size_t)cur * (BB * HH);

        {
            uint32_t st = sb + GRU_AST;
            CP_ASYNC16(st + ar * 48 + ahf * 16,
                       hb + (size_t)(mrow0 + ar) * 512 + ahf * 8);
            CP_ASYNC16(st + 6144 + ar * 48 + ahf * 16,
                       hl + (size_t)(mrow0 + ar) * 512 + ahf * 8);
            CP_COMMIT();
        }

        float acc[4][3][4];
#pragma unroll
        for (int i = 0; i < 4; i++)
#pragma unroll
            for (int g = 0; g < 3; g++)
#pragma unroll
                for (int z = 0; z < 4; z++) acc[i][g][z] = 0.f;

        for (int c = 0; c < 32; c++) {
            CP_WAIT0();
            __syncthreads();
            if (c < 31) {
                uint32_t st = sb + GRU_AST + (uint32_t)((c + 1) & 1) * 12288;
                const int kb = (c + 1) * 16 + ahf * 8;
                CP_ASYNC16(st + ar * 48 + ahf * 16,
                           hb + (size_t)(mrow0 + ar) * 512 + kb);
                CP_ASYNC16(st + 6144 + ar * 48 + ahf * 16,
                           hl + (size_t)(mrow0 + ar) * 512 + kb);
                CP_COMMIT();
            }
            const uint32_t cs = sb + GRU_AST + (uint32_t)(c & 1) * 12288;

            uint32_t bhf[3][2], blf[3][2];
#pragma unroll
            for (int g = 0; g < 3; g++) {
                int g16 = 2 * c + kbit;
                uint32_t phys = (uint32_t)lrB[g] * 1024 +
                                (uint32_t)((g16 ^ (lrB[g] & 7)) << 4);
                LDMX2(bhf[g][0], bhf[g][1], sb + GRU_WH + phys);
                LDMX2(blf[g][0], blf[g][1], sb + GRU_WL + phys);
            }
#pragma unroll
            for (int mi = 0; mi < 4; mi++) {
                uint32_t ah[4], al[4];
                LDMX4(ah[0], ah[1], ah[2], ah[3], cs + a_base + mi * 768);
                LDMX4(al[0], al[1], al[2], al[3], cs + 6144 + a_base + mi * 768);
#pragma unroll
                for (int g = 0; g < 3; g++) {
                    MMA_BF16(acc[mi][g], ah, bhf[g]);
                    MMA_BF16(acc[mi][g], ah, blf[g]);
                    MMA_BF16(acc[mi][g], al, bhf[g]);
                }
            }
        }
        __syncthreads();

#pragma unroll
        for (int mi = 0; mi < 4; mi++) {
#pragma unroll
            for (int hp = 0; hp < 2; hp++) {
                const int b = mrow0 + wm * 64 + mi * 16 + qrow + hp * 8;
                const size_t xb = ((size_t)b * SS + t) * GG + c0;
                float xr0 = g_xproj[xb],        xr1 = g_xproj[xb + 1];
                float xz0 = g_xproj[xb + 512],  xz1 = g_xproj[xb + 513];
                float xn0 = g_xproj[xb + 1024], xn1 = g_xproj[xb + 1025];
                float2 hold = *(const float2*)(g_hstate + (size_t)b * 512 + c0);
                float hr0 = acc[mi][0][hp * 2 + 0] + bhg[0][0];
                float hr1 = acc[mi][0][hp * 2 + 1] + bhg[0][1];
                float hz0 = acc[mi][1][hp * 2 + 0] + bhg[1][0];
                float hz1 = acc[mi][1][hp * 2 + 1] + bhg[1][1];
                float hn0 = acc[mi][2][hp * 2 + 0] + bhg[2][0];
                float hn1 = acc[mi][2][hp * 2 + 1] + bhg[2][1];
                float rg0 = 1.f / (1.f + expf(-(xr0 + hr0)));
                float rg1 = 1.f / (1.f + expf(-(xr1 + hr1)));
                float zg0 = 1.f / (1.f + expf(-(xz0 + hz0)));
                float zg1 = 1.f / (1.f + expf(-(xz1 + hz1)));
                float ng0 = tanhf(xn0 + rg0 * hn0);
                float ng1 = tanhf(xn1 + rg1 * hn1);
                float h0n = (1.f - zg0) * ng0 + zg0 * hold.x;
                float h1n = (1.f - zg1) * ng1 + zg1 * hold.y;
                float2 hsv = {h0n, h1n};
                *(float2*)(g_hstate + (size_t)b * 512 + c0) = hsv;
                __nv_bfloat16 p0 = __float2bfloat16(h0n);
                __nv_bfloat16 p1 = __float2bfloat16(h1n);
                __nv_bfloat16 q0 = __float2bfloat16(h0n - __bfloat162float(p0));
                __nv_bfloat16 q1 = __float2bfloat16(h1n - __bfloat162float(p1));
                __nv_bfloat162 ph = __halves2bfloat162(p0, p1);
                __nv_bfloat162 pl = __halves2bfloat162(q0, q1);
                size_t ob = (size_t)nxt * (BB * HH) + (size_t)b * 512 + c0;
                *(__nv_bfloat162*)(g_hbh + ob) = ph;
                *(__nv_bfloat162*)(g_hbl + ob) = pl;
                size_t oa = ((size_t)b * 128 + t) * 512 + c0;
                *(__nv_bfloat162*)(g_hh + oa) = ph;
                *(__nv_bfloat162*)(g_hl + oa) = pl;
            }
        }
        __threadfence();
        __syncthreads();
        if (tid == 0) {
            atomicAdd(&g_bar[mt], 1u);
            volatile unsigned* p = &g_bar[mt];
            while (*p < bar_target) {}
        }
        __syncthreads();
        __threadfence();
        bar_target += 16;
    }
}

// ---------------------------------------------------------------------------
// Kernel 3: attention via mma.sync. One CTA per b.  Wa consumed as fp32 and
// converted to bf16 hi/lo in SMEM on the fly (byte-neutral vs pre-split, but
// deletes the 2GB split kernel).  Exact col-sum C accumulated during convert.
// wm==1 warps skip mi==3 (rows 112..127 are padding).
// SMEM: ba 2048 | ws 2048 | C 512 | score 512 | 2 stages of
//       (AH 6144 | AL 6144 | BF32 10240 | BH 6144 | BL 6144) = 34816.
// ---------------------------------------------------------------------------
#define AT_BA 0
#define AT_WS 2048
#define AT_CS 4096
#define AT_SC 4608
#define AT_BASE 5120
#define AT_AH 0
#define AT_AL 6144
#define AT_BF 12288
#define AT_BH 22528
#define AT_BL 28672
#define AT_STG 34816
#define AT_SMEM (AT_BASE + 2 * AT_STG)

__global__ void __launch_bounds__(256, 1)
k_attn_mma(const float* __restrict__ reps, const int* __restrict__ counts,
           const int* __restrict__ users, const float* __restrict__ Wa,
           const float* __restrict__ ba, const float* __restrict__ Wsv,
           float* __restrict__ outp) {
    extern __shared__ char smx[];
    const uint32_t sb = smem_u32(smx);
    float* ba_s  = (float*)(smx + AT_BA);
    float* ws_s  = (float*)(smx + AT_WS);
    float* C_s   = (float*)(smx + AT_CS);
    float* score = (float*)(smx + AT_SC);
    const int tid = threadIdx.x;
    const int wid = tid >> 5, lane = tid & 31;
    const int wm = wid >> 2, wn = wid & 3;
    const int b = blockIdx.x;
    const int cnt = counts[b];
    const int u = users[b];

    ba_s[tid]       = ba[(size_t)u * 512 + tid];
    ba_s[tid + 256] = ba[(size_t)u * 512 + 256 + tid];
    ws_s[tid]       = Wsv[(size_t)u * 512 + tid];
    ws_s[tid + 256] = Wsv[(size_t)u * 512 + 256 + tid];
    if (tid < 128) score[tid] = 0.f;
    __syncthreads();

    const __nv_bfloat16* Ahg = g_hh + (size_t)b * 128 * 512;
    const __nv_bfloat16* Alg = g_hl + (size_t)b * 128 * 512;
    const float* Bg = Wa + (size_t)u * 512 * 512;

    const int tr = tid >> 1, tc = tid & 1;
    const uint32_t a_lane_off =
        (uint32_t)((wm * 64 + (lane & 15)) * 48 + (lane >> 4) * 16);
    const uint32_t b_lane_off =
        (uint32_t)((wn * 32 + (lane & 7) + (lane >> 4) * 8) * 48 +
                   ((lane >> 3) & 1) * 16);
    const int q = lane >> 2, cc = (lane & 3) * 2;
    const int mimax = (wm == 0) ? 4 : 3;

    // prefetch it = 0
    {
        uint32_t st = sb + AT_BASE;
        CP_ASYNC16(st + AT_AH + tr * 48 + tc * 16, Ahg + tr * 512 + tc * 8);
        CP_ASYNC16(st + AT_AL + tr * 48 + tc * 16, Alg + tr * 512 + tc * 8);
        CP_ASYNC16(st + AT_BF + tr * 80 + tc * 32,      Bg + (size_t)tr * 512 + tc * 8);
        CP_ASYNC16(st + AT_BF + tr * 80 + tc * 32 + 16, Bg + (size_t)tr * 512 + tc * 8 + 4);
        CP_COMMIT();
    }

    float acc[4][4][4];
    float cacc = 0.f;
    for (int it = 0; it < 128; it++) {
        const int np = it >> 5, c = it & 31;
        if (c == 0) {
#pragma unroll
            for (int i = 0; i < 4; i++)
#pragma unroll
                for (int j = 0; j < 4; j++)
#pragma unroll
                    for (int z = 0; z < 4; z++) acc[i][j][z] = 0.f;
            cacc = 0.f;
        }
        char* stc = smx + AT_BASE + (size_t)(it & 1) * AT_STG;
        const uint32_t cur = sb + AT_BASE + (uint32_t)(it & 1) * AT_STG;
        if (it < 127) {
            const int np2 = (it + 1) >> 5, c2 = (it + 1) & 31;
            const int k0 = c2 * 16;
            uint32_t st = sb + AT_BASE + (uint32_t)((it + 1) & 1) * AT_STG;
            const float* brow = Bg + (size_t)(np2 * 128 + tr) * 512 + k0 + tc * 8;
            CP_ASYNC16(st + AT_AH + tr * 48 + tc * 16,
                       Ahg + tr * 512 + k0 + tc * 8);
            CP_ASYNC16(st + AT_AL + tr * 48 + tc * 16,
                       Alg + tr * 512 + k0 + tc * 8);
            CP_ASYNC16(st + AT_BF + tr * 80 + tc * 32, brow);
            CP_ASYNC16(st + AT_BF + tr * 80 + tc * 32 + 16, brow + 4);
            CP_COMMIT();
            CP_WAIT1();
        } else {
            CP_WAIT0();
        }
        __syncthreads();

        // convert this chunk's B fp32 -> bf16 hi/lo, accumulate C partials
        {
            float4 v0 = *(const float4*)(stc + AT_BF + tr * 80 + tc * 32);
            float4 v1 = *(const float4*)(stc + AT_BF + tr * 80 + tc * 32 + 16);
            float f[8] = {v0.x, v0.y, v0.z, v0.w, v1.x, v1.y, v1.z, v1.w};
            cacc += f[0] + f[1] + f[2] + f[3] + f[4] + f[5] + f[6] + f[7];
            uint4 hv, lv;
            cvt8(f, hv, lv);
            *(uint4*)(stc + AT_BH + tr * 48 + tc * 16) = hv;
            *(uint4*)(stc + AT_BL + tr * 48 + tc * 16) = lv;
        }
        if (c == 31) {
            float tot = cacc + __shfl_xor_sync(0xffffffffu, cacc, 1);
            if (tc == 0) C_s[tr] = tot;
        }
        __syncthreads();

        uint32_t bh[4][2], bl[4][2];
        {
            uint32_t r0, r1, r2, r3;
            LDMX4(r0, r1, r2, r3, cur + AT_BH + b_lane_off);
            bh[0][0] = r0; bh[0][1] = r1; bh[1][0] = r2; bh[1][1] = r3;
            LDMX4(r0, r1, r2, r3, cur + AT_BH + b_lane_off + 16 * 48);
            bh[2][0] = r0; bh[2][1] = r1; bh[3][0] = r2; bh[3][1] = r3;
            LDMX4(r0, r1, r2, r3, cur + AT_BL + b_lane_off);
            bl[0][0] = r0; bl[0][1] = r1; bl[1][0] = r2; bl[1][1] = r3;
            LDMX4(r0, r1, r2, r3, cur + AT_BL + b_lane_off + 16 * 48);
            bl[2][0] = r0; bl[2][1] = r1; bl[3][0] = r2; bl[3][1] = r3;
        }
#pragma unroll
        for (int mi = 0; mi < 4; mi++) {
            if (mi >= mimax) break;           // rows 112..127 are padding
            uint32_t ah[4], al[4];
            LDMX4(ah[0], ah[1], ah[2], ah[3], cur + AT_AH + a_lane_off + mi * 16 * 48);
            LDMX4(al[0], al[1], al[2], al[3], cur + AT_AL + a_lane_off + mi * 16 * 48);
#pragma unroll
            for (int nj = 0; nj < 4; nj++) {
                MMA_BF16(acc[mi][nj], ah, bh[nj]);
                MMA_BF16(acc[mi][nj], ah, bl[nj]);
                MMA_BF16(acc[mi][nj], al, bh[nj]);
            }
        }

        if (c == 31) {
#pragma unroll
            for (int mi = 0; mi < 4; mi++) {
                if (mi >= mimax) break;
                const int s0 = wm * 64 + mi * 16 + q;
#pragma unroll
                for (int half = 0; half < 2; half++) {
                    const int s = s0 + half * 8;
                    const bool valid = (s < 100);
                    const float msk = (valid && s >= cnt) ? 1000000.0f : 0.0f;
                    float psum = 0.f;
#pragma unroll
                    for (int nj = 0; nj < 4; nj++) {
                        const int ol = wn * 32 + nj * 8 + cc;
                        const int o0 = np * 128 + ol;
                        float a0 = acc[mi][nj][half * 2 + 0] + ba_s[o0] - msk * C_s[ol];
                        float a1 = acc[mi][nj][half * 2 + 1] + ba_s[o0 + 1] - msk * C_s[ol + 1];
                        psum += ws_s[o0] * tanhf(a0) + ws_s[o0 + 1] * tanhf(a1);
                    }
                    psum += __shfl_xor_sync(0xffffffffu, psum, 1);
                    psum += __shfl_xor_sync(0xffffffffu, psum, 2);
                    if ((lane & 3) == 0 && valid) atomicAdd(&score[s], psum);
                }
            }
        }
    }
    __syncthreads();

    if (tid < 32) {
        float mx = -1e30f;
        for (int s = tid; s < 100; s += 32) mx = fmaxf(mx, score[s]);
#pragma unroll
        for (int o = 16; o > 0; o >>= 1) mx = fmaxf(mx, __shfl_xor_sync(0xffffffffu, mx, o));
        float ssum = 0.f;
        for (int s = tid; s < 100; s += 32) {
            float e = expf(score[s] - mx);
            score[s] = e;
            ssum += e;
        }
#pragma unroll
        for (int o = 16; o > 0; o >>= 1) ssum += __shfl_xor_sync(0xffffffffu, ssum, o);
        float inv = 1.f / ssum;
        for (int s = tid; s < 100; s += 32) score[s] *= inv;
    }
    __syncthreads();

    const float* rb = reps + (size_t)b * (SS * HH);
    for (int h = tid; h < 512; h += 256) {
        float a0 = 0.f;
        for (int s = 0; s < 100; s++) a0 += score[s] * rb[s * 512 + h];
        outp[(size_t)b * 512 + h] = a0;
    }
}

// ---------------------------------------------------------------------------
extern "C" void kernel_launch(void* const* d_in, const int* in_sizes, int n_in,
                              void* d_out, int out_size) {
    const float* reps   = (const float*)d_in[0];
    const float* hidden = (const float*)d_in[1];
    const int*   counts = (const int*)d_in[2];
    const int*   users  = (const int*)d_in[3];
    const float* W_ih   = (const float*)d_in[4];
    const float* W_hh   = (const float*)d_in[5];
    const float* b_ih   = (const float*)d_in[6];
    const float* b_hh   = (const float*)d_in[7];
    const float* Wa     = (const float*)d_in[8];
    const float* ba     = (const float*)d_in[9];
    const float* Ws     = (const float*)d_in[10];
    // d_in[11] = bs: additive per-row constant on scores -> softmax-invariant.
    float* out = (float*)d_out;

    cudaFuncSetAttribute(k_xproj_mma, cudaFuncAttributeMaxDynamicSharedMemorySize,
                         XP_SMEM);
    cudaFuncSetAttribute(k_gru_mma, cudaFuncAttributeMaxDynamicSharedMemorySize,
                         GRU_SMEM);
    cudaFuncSetAttribute(k_attn_mma, cudaFuncAttributeMaxDynamicSharedMemorySize,
                         AT_SMEM);

    __nv_bfloat16 *xh, *xl, *wh, *wl, *whhh, *whhl;
    void* barp;
    cudaGetSymbolAddress((void**)&xh, g_xh);
    cudaGetSymbolAddress((void**)&xl, g_xl);
    cudaGetSymbolAddress((void**)&wh, g_wh);
    cudaGetSymbolAddress((void**)&wl, g_wl);
    cudaGetSymbolAddress((void**)&whhh, g_whhh);
    cudaGetSymbolAddress((void**)&whhl, g_whhl);
    cudaGetSymbolAddress(&barp, g_bar);

    cudaMemsetAsync(barp, 0, 16 * sizeof(unsigned));

    const size_t nX  = (size_t)BB * SS * HH / 4;
    const size_t nW  = (size_t)GG * HH / 4;
    k_split<<<(unsigned)((nX + 255) / 256), 256>>>(reps, xh, xl, nX);
    k_split<<<(unsigned)((nW + 255) / 256), 256>>>(W_ih, wh, wl, nW);
    k_split<<<(unsigned)((nW + 255) / 256), 256>>>(W_hh, whhh, whhl, nW);

    dim3 g1(800, 6);
    k_xproj_mma<<<g1, 512, XP_SMEM>>>(b_ih);
    k_gru_mma<<<dim3(16, 8), 256, GRU_SMEM>>>(hidden, b_hh);
    k_attn_mma<<<BB, 256, AT_SMEM>>>(reps, counts, users, Wa, ba, Ws, out);
}